// round 3
// baseline (speedup 1.0000x reference)
#include <cuda_runtime.h>
#include <cstdint>

#define D_MODEL 1024
#define DIM 1024
#define DSTATE 16
#define SEQ_T 2048
#define NBATCH 2
#define BT (NBATCH*SEQ_T)      // 4096 rows
#define NCHUNK 16
#define TCHUNK (SEQ_T/NCHUNK)  // 128

// ------------------------- scratch (static device globals; no allocation) ---
__device__ float g_xn  [BT*D_MODEL];        // layernorm out
__device__ float g_xz  [BT*2*DIM];          // xn @ W_in
__device__ float g_xc  [BT*DIM];            // silu(conv(x_ssm))
__device__ float g_dt  [BT*DIM];            // softplus(xc@dt_w+b)
__device__ float g_bc  [BT*32];             // [Bm | Cm]
__device__ float g_bcw [DIM*32];            // [B_w | C_w] concat
__device__ float g_hend [NBATCH*NCHUNK*DSTATE*DIM];
__device__ float g_Pp   [NBATCH*NCHUNK*DIM];
__device__ float g_hinit[NBATCH*NCHUNK*DSTATE*DIM];
__device__ float g_yg  [BT*DIM];            // gated scan output

// --------------------------------------------------------------- layernorm --
__global__ void ln_kernel(const float* __restrict__ x,
                          const float* __restrict__ g,
                          const float* __restrict__ b) {
    int row = blockIdx.x;
    int tid = threadIdx.x;
    const float4* xr = (const float4*)(x + (size_t)row * D_MODEL);
    float4 v = xr[tid];
    float s  = v.x + v.y + v.z + v.w;
    float ss = v.x*v.x + v.y*v.y + v.z*v.z + v.w*v.w;
    #pragma unroll
    for (int o = 16; o; o >>= 1) {
        s  += __shfl_xor_sync(0xffffffffu, s,  o);
        ss += __shfl_xor_sync(0xffffffffu, ss, o);
    }
    __shared__ float sm[8], sm2[8];
    int w = tid >> 5, l = tid & 31;
    if (l == 0) { sm[w] = s; sm2[w] = ss; }
    __syncthreads();
    if (tid == 0) {
        float a = 0.f, a2 = 0.f;
        #pragma unroll
        for (int i = 0; i < 8; i++) { a += sm[i]; a2 += sm2[i]; }
        sm[0]  = a  * (1.0f / D_MODEL);
        sm2[0] = a2 * (1.0f / D_MODEL);
    }
    __syncthreads();
    float mu = sm[0];
    float var = sm2[0] - mu * mu;
    float rs = rsqrtf(var + 1e-5f);
    const float4* g4 = (const float4*)g;
    const float4* b4 = (const float4*)b;
    float4 gv = g4[tid], bv = b4[tid];
    float4 o;
    o.x = (v.x - mu) * rs * gv.x + bv.x;
    o.y = (v.y - mu) * rs * gv.y + bv.y;
    o.z = (v.z - mu) * rs * gv.z + bv.z;
    o.w = (v.w - mu) * rs * gv.w + bv.w;
    ((float4*)(g_xn + (size_t)row * D_MODEL))[tid] = o;
}

// -------------------------------------------------- causal dwconv + silu ----
__global__ void conv_silu_kernel(const float* __restrict__ cw,
                                 const float* __restrict__ cb) {
    int idx = blockIdx.x * blockDim.x + threadIdx.x;   // BT*DIM
    int di  = idx & (DIM - 1);
    int row = idx >> 10;                               // b*T + t
    int t   = row & (SEQ_T - 1);
    float4 w = ((const float4*)cw)[di];
    float acc = cb[di];
    const float* base = g_xz + row * (2 * DIM) + di;
    if (t >= 3) acc += w.x * base[-3 * 2 * DIM];
    if (t >= 2) acc += w.y * base[-2 * 2 * DIM];
    if (t >= 1) acc += w.z * base[-1 * 2 * DIM];
    acc += w.w * base[0];
    float sig = 1.f / (1.f + __expf(-acc));
    g_xc[idx] = acc * sig;
}

// -------------------------------------------------------- [B_w|C_w] concat --
__global__ void bcw_kernel(const float* __restrict__ Bw,
                           const float* __restrict__ Cw) {
    int idx = blockIdx.x * blockDim.x + threadIdx.x;   // DIM*32
    int j = idx & 31, k = idx >> 5;
    g_bcw[idx] = (j < 16) ? Bw[k * 16 + j] : Cw[k * 16 + (j - 16)];
}

// ----------------------------------------------------- tf32 mma.sync GEMM ---
__device__ __forceinline__ float to_tf32(float x) {
    uint32_t u;
    asm("cvt.rna.tf32.f32 %0, %1;" : "=r"(u) : "f"(x));
    return __uint_as_float(u);
}

__device__ __forceinline__ void mma_tf32(float* c, const uint32_t* a, const uint32_t* b) {
    asm volatile(
        "mma.sync.aligned.m16n8k8.row.col.f32.tf32.tf32.f32 "
        "{%0,%1,%2,%3}, {%4,%5,%6,%7}, {%8,%9}, {%0,%1,%2,%3};\n"
        : "+f"(c[0]), "+f"(c[1]), "+f"(c[2]), "+f"(c[3])
        : "r"(a[0]), "r"(a[1]), "r"(a[2]), "r"(a[3]), "r"(b[0]), "r"(b[1]));
}

// EPI: 0 = plain, 1 = softplus(acc + bias[col]), 2 = acc + addend[row,col]
template<int EPI>
__device__ __forceinline__ float epi_apply(float v, int row, int col, int N,
                                           const float* bias, const float* addend) {
    if (EPI == 1) {
        float s = v + bias[col];
        return (s > 20.f) ? s : log1pf(__expf(s));
    }
    if (EPI == 2) return v + addend[(size_t)row * N + col];
    return v;
}

template<int BM, int BN, int BK, int WM, int WN, int EPI>
__global__ void __launch_bounds__((BM/WM)*(BN/WN)*32)
gemm_kernel(const float* __restrict__ A, const float* __restrict__ Bg,
            float* __restrict__ Cg, int M, int N, int K,
            const float* __restrict__ bias, const float* __restrict__ addend)
{
    constexpr int WARPS_M = BM / WM;
    constexpr int WARPS_N = BN / WN;
    constexpr int NT = WARPS_M * WARPS_N * 32;
    constexpr int MD = WM / 16;
    constexpr int ND = WN / 8;
    static_assert(BK == 16, "BK must be 16");
    constexpr int AS = 36;            // A smem row stride (bank-spread, 16B aligned)
    constexpr int BS = BN + 8;        // B smem row stride
    constexpr int AV4 = BM * BK / 4;
    constexpr int APT = AV4 / NT;
    constexpr int BV4 = BK * BN / 4;
    constexpr int BPT = (BV4 + NT - 1) / NT;
    constexpr bool BFULL = (BV4 % NT) == 0;

    __shared__ float sA[BM * AS];
    __shared__ float sB[BK * BS];

    const int tid = threadIdx.x;
    const int bm = blockIdx.y * BM;
    const int bn = blockIdx.x * BN;
    const int warp = tid >> 5, lane = tid & 31;
    const int wm = (warp / WARPS_N) * WM;
    const int wn = (warp % WARPS_N) * WN;
    const int grp = lane >> 2, tg = lane & 3;

    float acc[MD][ND][4];
    #pragma unroll
    for (int i = 0; i < MD; i++)
        #pragma unroll
        for (int j = 0; j < ND; j++)
            #pragma unroll
            for (int e = 0; e < 4; e++) acc[i][j][e] = 0.f;

    float4 ra[APT], rb[BPT];
    const int KT = K / BK;

    // prologue: load tile 0
    #pragma unroll
    for (int i = 0; i < APT; i++) {
        int idx = tid + i * NT; int r = idx / (BK/4), c4 = idx % (BK/4);
        ra[i] = *(const float4*)(A + (size_t)(bm + r) * K + c4 * 4);
    }
    #pragma unroll
    for (int i = 0; i < BPT; i++) {
        int idx = tid + i * NT;
        if (BFULL || idx < BV4) {
            int r = idx / (BN/4), c4 = idx % (BN/4);
            rb[i] = *(const float4*)(Bg + (size_t)r * N + bn + c4 * 4);
        }
    }
    #pragma unroll
    for (int i = 0; i < APT; i++) {
        int idx = tid + i * NT; int r = idx / (BK/4), c4 = idx % (BK/4);
        float4 v = ra[i];
        v.x = to_tf32(v.x); v.y = to_tf32(v.y); v.z = to_tf32(v.z); v.w = to_tf32(v.w);
        *(float4*)(sA + r * AS + c4 * 4) = v;
    }
    #pragma unroll
    for (int i = 0; i < BPT; i++) {
        int idx = tid + i * NT;
        if (BFULL || idx < BV4) {
            int r = idx / (BN/4), c4 = idx % (BN/4);
            float4 v = rb[i];
            v.x = to_tf32(v.x); v.y = to_tf32(v.y); v.z = to_tf32(v.z); v.w = to_tf32(v.w);
            *(float4*)(sB + r * BS + c4 * 4) = v;
        }
    }
    __syncthreads();

    for (int kt = 0; kt < KT; kt++) {
        if (kt + 1 < KT) {
            int k0 = (kt + 1) * BK;
            #pragma unroll
            for (int i = 0; i < APT; i++) {
                int idx = tid + i * NT; int r = idx / (BK/4), c4 = idx % (BK/4);
                ra[i] = *(const float4*)(A + (size_t)(bm + r) * K + k0 + c4 * 4);
            }
            #pragma unroll
            for (int i = 0; i < BPT; i++) {
                int idx = tid + i * NT;
                if (BFULL || idx < BV4) {
                    int r = idx / (BN/4), c4 = idx % (BN/4);
                    rb[i] = *(const float4*)(Bg + (size_t)(k0 + r) * N + bn + c4 * 4);
                }
            }
        }
        #pragma unroll
        for (int ks = 0; ks < BK / 8; ks++) {
            uint32_t af[MD][4], bf[ND][2];
            #pragma unroll
            for (int md = 0; md < MD; md++) {
                const float* ap = sA + (wm + md * 16) * AS + ks * 8;
                af[md][0] = __float_as_uint(ap[ grp      * AS + tg    ]);
                af[md][1] = __float_as_uint(ap[(grp + 8) * AS + tg    ]);
                af[md][2] = __float_as_uint(ap[ grp      * AS + tg + 4]);
                af[md][3] = __float_as_uint(ap[(grp + 8) * AS + tg + 4]);
            }
            #pragma unroll
            for (int nd = 0; nd < ND; nd++) {
                const float* bp = sB + (ks * 8) * BS + wn + nd * 8 + grp;
                bf[nd][0] = __float_as_uint(bp[ tg      * BS]);
                bf[nd][1] = __float_as_uint(bp[(tg + 4) * BS]);
            }
            #pragma unroll
            for (int md = 0; md < MD; md++)
                #pragma unroll
                for (int nd = 0; nd < ND; nd++)
                    mma_tf32(acc[md][nd], af[md], bf[nd]);
        }
        __syncthreads();
        if (kt + 1 < KT) {
            #pragma unroll
            for (int i = 0; i < APT; i++) {
                int idx = tid + i * NT; int r = idx / (BK/4), c4 = idx % (BK/4);
                float4 v = ra[i];
                v.x = to_tf32(v.x); v.y = to_tf32(v.y); v.z = to_tf32(v.z); v.w = to_tf32(v.w);
                *(float4*)(sA + r * AS + c4 * 4) = v;
            }
            #pragma unroll
            for (int i = 0; i < BPT; i++) {
                int idx = tid + i * NT;
                if (BFULL || idx < BV4) {
                    int r = idx / (BN/4), c4 = idx % (BN/4);
                    float4 v = rb[i];
                    v.x = to_tf32(v.x); v.y = to_tf32(v.y); v.z = to_tf32(v.z); v.w = to_tf32(v.w);
                    *(float4*)(sB + r * BS + c4 * 4) = v;
                }
            }
            __syncthreads();
        }
    }

    // epilogue
    #pragma unroll
    for (int md = 0; md < MD; md++) {
        #pragma unroll
        for (int nd = 0; nd < ND; nd++) {
            int row0 = bm + wm + md * 16 + grp;
            int col  = bn + wn + nd * 8 + 2 * tg;
            float2 p;
            p.x = epi_apply<EPI>(acc[md][nd][0], row0, col,     N, bias, addend);
            p.y = epi_apply<EPI>(acc[md][nd][1], row0, col + 1, N, bias, addend);
            *(float2*)(Cg + (size_t)row0 * N + col) = p;
            float2 q;
            q.x = epi_apply<EPI>(acc[md][nd][2], row0 + 8, col,     N, bias, addend);
            q.y = epi_apply<EPI>(acc[md][nd][3], row0 + 8, col + 1, N, bias, addend);
            *(float2*)(Cg + (size_t)(row0 + 8) * N + col) = q;
        }
    }
}

// --------------------------------------------------------------- scan ------
// Phase A: per-(channel, chunk) local scan from h=0; record end state + decay product
__global__ void scanA_kernel(const float* __restrict__ logA) {
    int di = blockIdx.x * 128 + threadIdx.x;
    int c = blockIdx.y, b = blockIdx.z;
    float Av = -__expf(logA[di]);
    float h[DSTATE];
    #pragma unroll
    for (int s = 0; s < DSTATE; s++) h[s] = 0.f;
    float P = 1.f;
    int rbase = b * SEQ_T + c * TCHUNK;
    for (int t = 0; t < TCHUNK; t++) {
        int row = rbase + t;
        float dtv = g_dt[row * DIM + di];
        float xv  = g_xc[row * DIM + di];
        float decay = __expf(fminf(dtv * Av, 0.f));
        float u = dtv * xv;
        const float4* bc = (const float4*)(g_bc + row * 32);
        float4 b0 = bc[0], b1 = bc[1], b2 = bc[2], b3 = bc[3];
        float Bv[DSTATE] = {b0.x,b0.y,b0.z,b0.w, b1.x,b1.y,b1.z,b1.w,
                            b2.x,b2.y,b2.z,b2.w, b3.x,b3.y,b3.z,b3.w};
        P *= decay;
        #pragma unroll
        for (int s = 0; s < DSTATE; s++) h[s] = h[s] * decay + u * Bv[s];
    }
    int o = ((b * NCHUNK + c) * DSTATE) * DIM + di;
    #pragma unroll
    for (int s = 0; s < DSTATE; s++) g_hend[o + s * DIM] = h[s];
    g_Pp[(b * NCHUNK + c) * DIM + di] = P;
}

// Phase B: sequential cross-chunk combine (exact — recurrence is linear in h0)
__global__ void combine_kernel() {
    int idx = blockIdx.x * 256 + threadIdx.x;   // NBATCH*DSTATE*DIM
    int di = idx % DIM;
    int s  = (idx / DIM) % DSTATE;
    int b  = idx / (DIM * DSTATE);
    float h = 0.f;
    g_hinit[((b * NCHUNK + 0) * DSTATE + s) * DIM + di] = 0.f;
    for (int c = 1; c < NCHUNK; c++) {
        float he = g_hend[((b * NCHUNK + c - 1) * DSTATE + s) * DIM + di];
        float Pv = g_Pp [ (b * NCHUNK + c - 1) * DIM + di];
        h = he + Pv * h;
        g_hinit[((b * NCHUNK + c) * DSTATE + s) * DIM + di] = h;
    }
}

// Phase C: rerun scan from exact initial state, fuse y + x*D and silu(z) gate
__global__ void scanC_kernel(const float* __restrict__ logA,
                             const float* __restrict__ Dp) {
    int di = blockIdx.x * 128 + threadIdx.x;
    int c = blockIdx.y, b = blockIdx.z;
    float Av = -__expf(logA[di]);
    float Dv = Dp[di];
    float h[DSTATE];
    int o = ((b * NCHUNK + c) * DSTATE) * DIM + di;
    #pragma unroll
    for (int s = 0; s < DSTATE; s++) h[s] = g_hinit[o + s * DIM];
    int rbase = b * SEQ_T + c * TCHUNK;
    for (int t = 0; t < TCHUNK; t++) {
        int row = rbase + t;
        float dtv = g_dt[row * DIM + di];
        float xv  = g_xc[row * DIM + di];
        float decay = __expf(fminf(dtv * Av, 0.f));
        float u = dtv * xv;
        const float4* bc = (const float4*)(g_bc + row * 32);
        float4 b0 = bc[0], b1 = bc[1], b2 = bc[2], b3 = bc[3];
        float4 c0 = bc[4], c1 = bc[5], c2 = bc[6], c3 = bc[7];
        float Bv[DSTATE] = {b0.x,b0.y,b0.z,b0.w, b1.x,b1.y,b1.z,b1.w,
                            b2.x,b2.y,b2.z,b2.w, b3.x,b3.y,b3.z,b3.w};
        float Cv[DSTATE] = {c0.x,c0.y,c0.z,c0.w, c1.x,c1.y,c1.z,c1.w,
                            c2.x,c2.y,c2.z,c2.w, c3.x,c3.y,c3.z,c3.w};
        float y = 0.f;
        #pragma unroll
        for (int s = 0; s < DSTATE; s++) {
            h[s] = h[s] * decay + u * Bv[s];
            y += h[s] * Cv[s];
        }
        float zv = g_xz[row * (2 * DIM) + DIM + di];
        float sg = zv / (1.f + __expf(-zv));
        g_yg[row * DIM + di] = (y + xv * Dv) * sg;
    }
}

// ----------------------------------------------------------------- launch ---
extern "C" void kernel_launch(void* const* d_in, const int* in_sizes, int n_in,
                              void* d_out, int out_size) {
    const float* x      = (const float*)d_in[0];
    const float* ln_g   = (const float*)d_in[1];
    const float* ln_b   = (const float*)d_in[2];
    const float* W_in   = (const float*)d_in[3];
    const float* conv_w = (const float*)d_in[4];
    const float* conv_b = (const float*)d_in[5];
    const float* dt_w   = (const float*)d_in[6];
    const float* dt_b   = (const float*)d_in[7];
    const float* B_w    = (const float*)d_in[8];
    const float* C_w    = (const float*)d_in[9];
    const float* log_A  = (const float*)d_in[10];
    const float* D_par  = (const float*)d_in[11];
    const float* W_out  = (const float*)d_in[12];
    float* out = (float*)d_out;

    float *p_xn, *p_xz, *p_xc, *p_dt, *p_bc, *p_bcw, *p_yg;
    cudaGetSymbolAddress((void**)&p_xn,  g_xn);
    cudaGetSymbolAddress((void**)&p_xz,  g_xz);
    cudaGetSymbolAddress((void**)&p_xc,  g_xc);
    cudaGetSymbolAddress((void**)&p_dt,  g_dt);
    cudaGetSymbolAddress((void**)&p_bc,  g_bc);
    cudaGetSymbolAddress((void**)&p_bcw, g_bcw);
    cudaGetSymbolAddress((void**)&p_yg,  g_yg);

    // 1. layernorm
    ln_kernel<<<BT, 256>>>(x, ln_g, ln_b);

    // 2. xz = xn @ W_in   [4096 x 2048]
    gemm_kernel<128,128,16,32,64,0><<<dim3(2*DIM/128, BT/128), 256>>>(
        p_xn, W_in, p_xz, BT, 2*DIM, D_MODEL, nullptr, nullptr);

    // 3. weight concat + causal depthwise conv + silu
    bcw_kernel<<<DIM*32/256, 256>>>(B_w, C_w);
    conv_silu_kernel<<<BT*DIM/256, 256>>>(conv_w, conv_b);

    // 4. dt = softplus(xc @ dt_w + dt_b)
    gemm_kernel<128,128,16,32,64,1><<<dim3(DIM/128, BT/128), 256>>>(
        p_xc, dt_w, p_dt, BT, DIM, DIM, dt_b, nullptr);

    // 5. [Bm|Cm] = xc @ [B_w|C_w]   [4096 x 32]
    gemm_kernel<128,32,16,16,32,0><<<dim3(1, BT/128), 256>>>(
        p_xc, p_bcw, p_bc, BT, 32, DIM, nullptr, nullptr);

    // 6. chunked selective scan (exact)
    scanA_kernel<<<dim3(DIM/128, NCHUNK, NBATCH), 128>>>(log_A);
    combine_kernel<<<NBATCH*DSTATE*DIM/256, 256>>>();
    scanC_kernel<<<dim3(DIM/128, NCHUNK, NBATCH), 128>>>(log_A, D_par);

    // 7. out = x + yg @ W_out
    gemm_kernel<128,128,16,32,64,2><<<dim3(DIM/128, BT/128), 256>>>(
        p_yg, W_out, out, BT, DIM, DIM, nullptr, x);
}

// round 7
// speedup vs baseline: 1.4217x; 1.4217x over previous
#include <cuda_runtime.h>
#include <cstdint>

#define D_MODEL 1024
#define DIM 1024
#define DSTATE 16
#define SEQ_T 2048
#define NBATCH 2
#define BT (NBATCH*SEQ_T)      // 4096 rows
#define NCHUNK 64
#define TCHUNK (SEQ_T/NCHUNK)  // 32

// ------------------------- scratch (static device globals; no allocation) ---
__device__ float g_xn  [BT*D_MODEL];        // layernorm out (tf32-rounded)
__device__ float g_xz  [BT*2*DIM];          // xn @ W_in (fp32)
__device__ float g_xc  [BT*DIM];            // silu(conv(x_ssm)) fp32 (scan input)
__device__ float g_xct [BT*DIM];            // same, tf32-rounded (GEMM input)
__device__ float g_dt  [BT*DIM];            // softplus(xc@dt_w+b) fp32
__device__ float g_bc  [BT*32];             // [Bm | Cm] fp32
__device__ float g_bcw [DIM*32];            // [B_w | C_w] concat, tf32-rounded
__device__ float g_w1t [D_MODEL*2*DIM];     // W_in  tf32-rounded
__device__ float g_wdt [DIM*DIM];           // dt_w  tf32-rounded
__device__ float g_wot [DIM*D_MODEL];       // W_out tf32-rounded
__device__ float g_hend [NBATCH*NCHUNK*DSTATE*DIM];
__device__ float g_Pp   [NBATCH*NCHUNK*DIM];
__device__ float g_hinit[NBATCH*NCHUNK*DSTATE*DIM];
__device__ float g_yg  [BT*DIM];            // gated scan output (tf32-rounded)

__device__ __forceinline__ float to_tf32(float x) {
    uint32_t u;
    asm("cvt.rna.tf32.f32 %0, %1;" : "=r"(u) : "f"(x));
    return __uint_as_float(u);
}

// ------------------------------------------------ tf32 rounding of weights --
__global__ void cvt_kernel(const float* __restrict__ src, float* __restrict__ dst) {
    int i = blockIdx.x * 256 + threadIdx.x;
    float4 v = ((const float4*)src)[i];
    v.x = to_tf32(v.x); v.y = to_tf32(v.y); v.z = to_tf32(v.z); v.w = to_tf32(v.w);
    ((float4*)dst)[i] = v;
}

// --------------------------------------------------------------- layernorm --
__global__ void ln_kernel(const float* __restrict__ x,
                          const float* __restrict__ g,
                          const float* __restrict__ b) {
    int row = blockIdx.x;
    int tid = threadIdx.x;
    const float4* xr = (const float4*)(x + (size_t)row * D_MODEL);
    float4 v = xr[tid];
    float s  = v.x + v.y + v.z + v.w;
    float ss = v.x*v.x + v.y*v.y + v.z*v.z + v.w*v.w;
    #pragma unroll
    for (int o = 16; o; o >>= 1) {
        s  += __shfl_xor_sync(0xffffffffu, s,  o);
        ss += __shfl_xor_sync(0xffffffffu, ss, o);
    }
    __shared__ float sm[8], sm2[8];
    int w = tid >> 5, l = tid & 31;
    if (l == 0) { sm[w] = s; sm2[w] = ss; }
    __syncthreads();
    if (tid == 0) {
        float a = 0.f, a2 = 0.f;
        #pragma unroll
        for (int i = 0; i < 8; i++) { a += sm[i]; a2 += sm2[i]; }
        sm[0]  = a  * (1.0f / D_MODEL);
        sm2[0] = a2 * (1.0f / D_MODEL);
    }
    __syncthreads();
    float mu = sm[0];
    float var = sm2[0] - mu * mu;
    float rs = rsqrtf(var + 1e-5f);
    const float4* g4 = (const float4*)g;
    const float4* b4 = (const float4*)b;
    float4 gv = g4[tid], bv = b4[tid];
    float4 o;
    o.x = to_tf32((v.x - mu) * rs * gv.x + bv.x);
    o.y = to_tf32((v.y - mu) * rs * gv.y + bv.y);
    o.z = to_tf32((v.z - mu) * rs * gv.z + bv.z);
    o.w = to_tf32((v.w - mu) * rs * gv.w + bv.w);
    ((float4*)(g_xn + (size_t)row * D_MODEL))[tid] = o;
}

// -------------------------------------------------- causal dwconv + silu ----
__global__ void conv_silu_kernel(const float* __restrict__ cw,
                                 const float* __restrict__ cb) {
    int idx = blockIdx.x * 256 + threadIdx.x;          // BT*DIM/4 elements
    int di4 = idx & (DIM / 4 - 1);                     // 0..255
    int row = idx >> 8;                                // b*T + t
    int t   = row & (SEQ_T - 1);
    const float4* w4 = (const float4*)cw + di4 * 4;
    float4 w0 = w4[0], w1 = w4[1], w2 = w4[2], w3 = w4[3];
    float4 bias = ((const float4*)cb)[di4];
    const float* base = g_xz + (size_t)row * (2 * DIM) + di4 * 4;
    float4 zero = make_float4(0.f, 0.f, 0.f, 0.f);
    float4 r0 = (t >= 3) ? *(const float4*)(base - 3 * 2 * DIM) : zero;
    float4 r1 = (t >= 2) ? *(const float4*)(base - 2 * 2 * DIM) : zero;
    float4 r2 = (t >= 1) ? *(const float4*)(base - 1 * 2 * DIM) : zero;
    float4 r3 = *(const float4*)(base);
    float4 a;
    a.x = bias.x + w0.x*r0.x + w0.y*r1.x + w0.z*r2.x + w0.w*r3.x;
    a.y = bias.y + w1.x*r0.y + w1.y*r1.y + w1.z*r2.y + w1.w*r3.y;
    a.z = bias.z + w2.x*r0.z + w2.y*r1.z + w2.z*r2.z + w2.w*r3.z;
    a.w = bias.w + w3.x*r0.w + w3.y*r1.w + w3.z*r2.w + w3.w*r3.w;
    a.x = a.x / (1.f + __expf(-a.x));
    a.y = a.y / (1.f + __expf(-a.y));
    a.z = a.z / (1.f + __expf(-a.z));
    a.w = a.w / (1.f + __expf(-a.w));
    ((float4*)g_xc)[idx] = a;
    float4 at;
    at.x = to_tf32(a.x); at.y = to_tf32(a.y); at.z = to_tf32(a.z); at.w = to_tf32(a.w);
    ((float4*)g_xct)[idx] = at;
}

// -------------------------------------------------------- [B_w|C_w] concat --
__global__ void bcw_kernel(const float* __restrict__ Bw,
                           const float* __restrict__ Cw) {
    int idx = blockIdx.x * 256 + threadIdx.x;   // DIM*32
    int j = idx & 31, k = idx >> 5;
    float v = (j < 16) ? Bw[k * 16 + j] : Cw[k * 16 + (j - 16)];
    g_bcw[idx] = to_tf32(v);
}

// ----------------------------------------------------- tf32 mma.sync GEMM ---
__device__ __forceinline__ void mma_tf32(float* c, const uint32_t* a, const uint32_t* b) {
    asm volatile(
        "mma.sync.aligned.m16n8k8.row.col.f32.tf32.tf32.f32 "
        "{%0,%1,%2,%3}, {%4,%5,%6,%7}, {%8,%9}, {%0,%1,%2,%3};\n"
        : "+f"(c[0]), "+f"(c[1]), "+f"(c[2]), "+f"(c[3])
        : "r"(a[0]), "r"(a[1]), "r"(a[2]), "r"(a[3]), "r"(b[0]), "r"(b[1]));
}

// EPI: 0 = plain, 1 = softplus(acc + bias[col]), 2 = acc + addend[row,col]
template<int EPI>
__device__ __forceinline__ float epi_apply(float v, int row, int col, int N,
                                           const float* bias, const float* addend) {
    if (EPI == 1) {
        float s = v + bias[col];
        return (s > 20.f) ? s : log1pf(__expf(s));
    }
    if (EPI == 2) return v + addend[(size_t)row * N + col];
    return v;
}

// 3-stage cp.async multistage GEMM. Inputs must already be tf32-rounded.
// Group discipline: EVERY mainloop iteration commits exactly one group (empty
// in the tail), so wait_group 1 always guarantees the next stage is resident.
template<int BM, int BN, int BK, int WM, int WN, int EPI>
__global__ void __launch_bounds__((BM/WM)*(BN/WN)*32)
gemm_kernel(const float* __restrict__ A, const float* __restrict__ Bg,
            float* __restrict__ Cg, int M, int N, int K,
            const float* __restrict__ bias, const float* __restrict__ addend)
{
    constexpr int WARPS_M = BM / WM;
    constexpr int WARPS_N = BN / WN;
    constexpr int NT = WARPS_M * WARPS_N * 32;
    constexpr int MD = WM / 16;
    constexpr int ND = WN / 8;
    static_assert(BK == 32, "BK must be 32");
    constexpr int AS = BK + 4;        // 36: bank-spread
    constexpr int BS = BN + 8;
    constexpr int STAGES = 3;
    constexpr int ASZ = BM * AS;
    constexpr int BSZ = BK * BS;
    constexpr int AV4 = BM * BK / 4;
    constexpr int APT = AV4 / NT;
    constexpr int BV4 = BK * BN / 4;
    constexpr int BPT = (BV4 + NT - 1) / NT;
    constexpr bool BFULL = (BV4 % NT) == 0;

    extern __shared__ float smem[];
    float* sAbase = smem;
    float* sBbase = smem + STAGES * ASZ;

    const int tid = threadIdx.x;
    const int bm = blockIdx.y * BM;
    const int bn = blockIdx.x * BN;
    const int warp = tid >> 5, lane = tid & 31;
    const int wm = (warp / WARPS_N) * WM;
    const int wn = (warp % WARPS_N) * WN;
    const int grp = lane >> 2, tg = lane & 3;
    const int KT = K / BK;

    float acc[MD][ND][4];
    #pragma unroll
    for (int i = 0; i < MD; i++)
        #pragma unroll
        for (int j = 0; j < ND; j++)
            #pragma unroll
            for (int e = 0; e < 4; e++) acc[i][j][e] = 0.f;

    auto issue = [&](int kt, int stage) {
        int k0 = kt * BK;
        float* sA = sAbase + stage * ASZ;
        float* sB = sBbase + stage * BSZ;
        #pragma unroll
        for (int i = 0; i < APT; i++) {
            int idx = tid + i * NT;
            int r = idx / (BK / 4), c4 = idx % (BK / 4);
            uint32_t dst = (uint32_t)__cvta_generic_to_shared(sA + r * AS + c4 * 4);
            const float* src = A + (size_t)(bm + r) * K + k0 + c4 * 4;
            asm volatile("cp.async.cg.shared.global [%0], [%1], 16;\n"
                         :: "r"(dst), "l"(src));
        }
        #pragma unroll
        for (int i = 0; i < BPT; i++) {
            int idx = tid + i * NT;
            if (BFULL || idx < BV4) {
                int r = idx / (BN / 4), c4 = idx % (BN / 4);
                uint32_t dst = (uint32_t)__cvta_generic_to_shared(sB + r * BS + c4 * 4);
                const float* src = Bg + (size_t)(k0 + r) * N + bn + c4 * 4;
                asm volatile("cp.async.cg.shared.global [%0], [%1], 16;\n"
                             :: "r"(dst), "l"(src));
            }
        }
        asm volatile("cp.async.commit_group;\n" ::: "memory");
    };

    issue(0, 0);
    issue(1, 1);
    asm volatile("cp.async.wait_group 1;\n" ::: "memory");
    __syncthreads();

    for (int kt = 0; kt < KT; kt++) {
        int stage = kt % STAGES;
        if (kt + 2 < KT) {
            issue(kt + 2, (kt + 2) % STAGES);
        } else {
            // tail: empty group keeps the wait_group accounting uniform
            asm volatile("cp.async.commit_group;\n" ::: "memory");
        }
        const float* sA = sAbase + stage * ASZ;
        const float* sB = sBbase + stage * BSZ;
        #pragma unroll
        for (int ks = 0; ks < BK / 8; ks++) {
            uint32_t af[MD][4], bf[ND][2];
            #pragma unroll
            for (int md = 0; md < MD; md++) {
                const float* ap = sA + (wm + md * 16) * AS + ks * 8;
                af[md][0] = __float_as_uint(ap[ grp      * AS + tg    ]);
                af[md][1] = __float_as_uint(ap[(grp + 8) * AS + tg    ]);
                af[md][2] = __float_as_uint(ap[ grp      * AS + tg + 4]);
                af[md][3] = __float_as_uint(ap[(grp + 8) * AS + tg + 4]);
            }
            #pragma unroll
            for (int nd = 0; nd < ND; nd++) {
                const float* bp = sB + (ks * 8) * BS + wn + nd * 8 + grp;
                bf[nd][0] = __float_as_uint(bp[ tg      * BS]);
                bf[nd][1] = __float_as_uint(bp[(tg + 4) * BS]);
            }
            #pragma unroll
            for (int md = 0; md < MD; md++)
                #pragma unroll
                for (int nd = 0; nd < ND; nd++)
                    mma_tf32(acc[md][nd], af[md], bf[nd]);
        }
        asm volatile("cp.async.wait_group 1;\n" ::: "memory");
        __syncthreads();
    }

    // epilogue
    #pragma unroll
    for (int md = 0; md < MD; md++) {
        #pragma unroll
        for (int nd = 0; nd < ND; nd++) {
            int row0 = bm + wm + md * 16 + grp;
            int col  = bn + wn + nd * 8 + 2 * tg;
            float2 p;
            p.x = epi_apply<EPI>(acc[md][nd][0], row0, col,     N, bias, addend);
            p.y = epi_apply<EPI>(acc[md][nd][1], row0, col + 1, N, bias, addend);
            *(float2*)(Cg + (size_t)row0 * N + col) = p;
            float2 q;
            q.x = epi_apply<EPI>(acc[md][nd][2], row0 + 8, col,     N, bias, addend);
            q.y = epi_apply<EPI>(acc[md][nd][3], row0 + 8, col + 1, N, bias, addend);
            *(float2*)(Cg + (size_t)(row0 + 8) * N + col) = q;
        }
    }
}

// --------------------------------------------------------------- scan ------
__global__ void scanA_kernel(const float* __restrict__ logA) {
    int di = blockIdx.x * 128 + threadIdx.x;
    int c = blockIdx.y, b = blockIdx.z;
    float Av = -__expf(logA[di]);
    float h[DSTATE];
    #pragma unroll
    for (int s = 0; s < DSTATE; s++) h[s] = 0.f;
    float P = 1.f;
    int rbase = b * SEQ_T + c * TCHUNK;
    for (int t = 0; t < TCHUNK; t++) {
        int row = rbase + t;
        float dtv = g_dt[row * DIM + di];
        float xv  = g_xc[row * DIM + di];
        float decay = __expf(fminf(dtv * Av, 0.f));
        float u = dtv * xv;
        const float4* bc = (const float4*)(g_bc + row * 32);
        float4 b0 = bc[0], b1 = bc[1], b2 = bc[2], b3 = bc[3];
        float Bv[DSTATE] = {b0.x,b0.y,b0.z,b0.w, b1.x,b1.y,b1.z,b1.w,
                            b2.x,b2.y,b2.z,b2.w, b3.x,b3.y,b3.z,b3.w};
        P *= decay;
        #pragma unroll
        for (int s = 0; s < DSTATE; s++) h[s] = h[s] * decay + u * Bv[s];
    }
    int o = ((b * NCHUNK + c) * DSTATE) * DIM + di;
    #pragma unroll
    for (int s = 0; s < DSTATE; s++) g_hend[o + s * DIM] = h[s];
    g_Pp[(b * NCHUNK + c) * DIM + di] = P;
}

__global__ void combine_kernel() {
    int idx = blockIdx.x * 256 + threadIdx.x;   // NBATCH*DSTATE*DIM
    int di = idx % DIM;
    int s  = (idx / DIM) % DSTATE;
    int b  = idx / (DIM * DSTATE);
    float h = 0.f;
    g_hinit[((b * NCHUNK + 0) * DSTATE + s) * DIM + di] = 0.f;
    for (int c = 1; c < NCHUNK; c++) {
        float he = g_hend[((b * NCHUNK + c - 1) * DSTATE + s) * DIM + di];
        float Pv = g_Pp [ (b * NCHUNK + c - 1) * DIM + di];
        h = he + Pv * h;
        g_hinit[((b * NCHUNK + c) * DSTATE + s) * DIM + di] = h;
    }
}

__global__ void scanC_kernel(const float* __restrict__ logA,
                             const float* __restrict__ Dp) {
    int di = blockIdx.x * 128 + threadIdx.x;
    int c = blockIdx.y, b = blockIdx.z;
    float Av = -__expf(logA[di]);
    float Dv = Dp[di];
    float h[DSTATE];
    int o = ((b * NCHUNK + c) * DSTATE) * DIM + di;
    #pragma unroll
    for (int s = 0; s < DSTATE; s++) h[s] = g_hinit[o + s * DIM];
    int rbase = b * SEQ_T + c * TCHUNK;
    for (int t = 0; t < TCHUNK; t++) {
        int row = rbase + t;
        float dtv = g_dt[row * DIM + di];
        float xv  = g_xc[row * DIM + di];
        float decay = __expf(fminf(dtv * Av, 0.f));
        float u = dtv * xv;
        const float4* bc = (const float4*)(g_bc + row * 32);
        float4 b0 = bc[0], b1 = bc[1], b2 = bc[2], b3 = bc[3];
        float4 c0 = bc[4], c1 = bc[5], c2 = bc[6], c3 = bc[7];
        float Bv[DSTATE] = {b0.x,b0.y,b0.z,b0.w, b1.x,b1.y,b1.z,b1.w,
                            b2.x,b2.y,b2.z,b2.w, b3.x,b3.y,b3.z,b3.w};
        float Cv[DSTATE] = {c0.x,c0.y,c0.z,c0.w, c1.x,c1.y,c1.z,c1.w,
                            c2.x,c2.y,c2.z,c2.w, c3.x,c3.y,c3.z,c3.w};
        float y = 0.f;
        #pragma unroll
        for (int s = 0; s < DSTATE; s++) {
            h[s] = h[s] * decay + u * Bv[s];
            y += h[s] * Cv[s];
        }
        float zv = g_xz[row * (2 * DIM) + DIM + di];
        float sg = zv / (1.f + __expf(-zv));
        g_yg[row * DIM + di] = to_tf32((y + xv * Dv) * sg);
    }
}

// ----------------------------------------------------------------- launch ---
static inline int gemm_smem_bytes(int BM, int BN, int BK) {
    return 3 * (BM * (BK + 4) + BK * (BN + 8)) * (int)sizeof(float);
}

extern "C" void kernel_launch(void* const* d_in, const int* in_sizes, int n_in,
                              void* d_out, int out_size) {
    const float* x      = (const float*)d_in[0];
    const float* ln_g   = (const float*)d_in[1];
    const float* ln_b   = (const float*)d_in[2];
    const float* W_in   = (const float*)d_in[3];
    const float* conv_w = (const float*)d_in[4];
    const float* conv_b = (const float*)d_in[5];
    const float* dt_w   = (const float*)d_in[6];
    const float* dt_b   = (const float*)d_in[7];
    const float* B_w    = (const float*)d_in[8];
    const float* C_w    = (const float*)d_in[9];
    const float* log_A  = (const float*)d_in[10];
    const float* D_par  = (const float*)d_in[11];
    const float* W_out  = (const float*)d_in[12];
    float* out = (float*)d_out;

    float *p_xn, *p_xz, *p_xc, *p_xct, *p_dt, *p_bc, *p_bcw, *p_yg;
    float *p_w1t, *p_wdt, *p_wot;
    cudaGetSymbolAddress((void**)&p_xn,  g_xn);
    cudaGetSymbolAddress((void**)&p_xz,  g_xz);
    cudaGetSymbolAddress((void**)&p_xc,  g_xc);
    cudaGetSymbolAddress((void**)&p_xct, g_xct);
    cudaGetSymbolAddress((void**)&p_dt,  g_dt);
    cudaGetSymbolAddress((void**)&p_bc,  g_bc);
    cudaGetSymbolAddress((void**)&p_bcw, g_bcw);
    cudaGetSymbolAddress((void**)&p_yg,  g_yg);
    cudaGetSymbolAddress((void**)&p_w1t, g_w1t);
    cudaGetSymbolAddress((void**)&p_wdt, g_wdt);
    cudaGetSymbolAddress((void**)&p_wot, g_wot);

    int smem_big   = gemm_smem_bytes(128, 128, 32);
    int smem_small = gemm_smem_bytes(64, 32, 32);
    cudaFuncSetAttribute(gemm_kernel<128,128,32,32,64,0>,
                         cudaFuncAttributeMaxDynamicSharedMemorySize, smem_big);
    cudaFuncSetAttribute(gemm_kernel<128,128,32,32,64,1>,
                         cudaFuncAttributeMaxDynamicSharedMemorySize, smem_big);
    cudaFuncSetAttribute(gemm_kernel<128,128,32,32,64,2>,
                         cudaFuncAttributeMaxDynamicSharedMemorySize, smem_big);
    cudaFuncSetAttribute(gemm_kernel<64,32,32,32,16,0>,
                         cudaFuncAttributeMaxDynamicSharedMemorySize, smem_small);

    // 0. tf32-round the GEMM weights
    cvt_kernel<<<(D_MODEL*2*DIM/4)/256, 256>>>(W_in,  p_w1t);
    cvt_kernel<<<(DIM*DIM/4)/256,       256>>>(dt_w,  p_wdt);
    cvt_kernel<<<(DIM*D_MODEL/4)/256,   256>>>(W_out, p_wot);
    bcw_kernel<<<DIM*32/256, 256>>>(B_w, C_w);

    // 1. layernorm (tf32-rounded output)
    ln_kernel<<<BT, 256>>>(x, ln_g, ln_b);

    // 2. xz = xn @ W_in   [4096 x 2048]
    gemm_kernel<128,128,32,32,64,0><<<dim3(2*DIM/128, BT/128), 256, smem_big>>>(
        p_xn, p_w1t, p_xz, BT, 2*DIM, D_MODEL, nullptr, nullptr);

    // 3. causal depthwise conv + silu (fp32 + tf32 copies)
    conv_silu_kernel<<<(BT*DIM/4)/256, 256>>>(conv_w, conv_b);

    // 4. dt = softplus(xct @ dt_w + dt_b)
    gemm_kernel<128,128,32,32,64,1><<<dim3(DIM/128, BT/128), 256, smem_big>>>(
        p_xct, p_wdt, p_dt, BT, DIM, DIM, dt_b, nullptr);

    // 5. [Bm|Cm] = xct @ [B_w|C_w]   [4096 x 32]
    gemm_kernel<64,32,32,32,16,0><<<dim3(1, BT/64), 128, smem_small>>>(
        p_xct, p_bcw, p_bc, BT, 32, DIM, nullptr, nullptr);

    // 6. chunked selective scan (exact; NCHUNK=64 for occupancy)
    scanA_kernel<<<dim3(DIM/128, NCHUNK, NBATCH), 128>>>(log_A);
    combine_kernel<<<NBATCH*DSTATE*DIM/256, 256>>>();
    scanC_kernel<<<dim3(DIM/128, NCHUNK, NBATCH), 128>>>(log_A, D_par);

    // 7. out = x + yg @ W_out
    gemm_kernel<128,128,32,32,64,2><<<dim3(DIM/128, BT/128), 256, smem_big>>>(
        p_yg, p_wot, out, BT, DIM, DIM, nullptr, x);
}

// round 10
// speedup vs baseline: 1.5222x; 1.0707x over previous
#include <cuda_runtime.h>
#include <cstdint>

#define D_MODEL 1024
#define DIM 1024
#define DSTATE 16
#define SEQ_T 2048
#define NBATCH 2
#define BT (NBATCH*SEQ_T)      // 4096 rows
#define NCHUNK 64
#define TCHUNK (SEQ_T/NCHUNK)  // 32

// ------------------------- scratch (static device globals; no allocation) ---
__device__ float g_xn  [BT*D_MODEL];        // layernorm out (tf32-rounded)
__device__ float g_xz  [BT*2*DIM];          // xn @ W_in (fp32)
__device__ float g_xc  [BT*DIM];            // silu(conv) fp32 (scan input)
__device__ float g_xct [BT*DIM];            // same, tf32-rounded (GEMM input)
__device__ float g_dt  [BT*DIM];
__device__ float g_bc  [BT*32];             // [Bm | Cm]
__device__ float g_bcw [DIM*32];            // [B_w | C_w] concat, tf32-rounded
__device__ float g_w1t [D_MODEL*2*DIM];     // W_in  tf32-rounded
__device__ float g_wdt [DIM*DIM];           // dt_w  tf32-rounded
__device__ float g_wot [DIM*D_MODEL];       // W_out tf32-rounded
__device__ float g_hend [NBATCH*NCHUNK*DSTATE*DIM];
__device__ float g_Pp   [NBATCH*NCHUNK*DIM];
__device__ float g_hinit[NBATCH*NCHUNK*DSTATE*DIM];
__device__ float g_yg  [BT*DIM];            // gated scan output (tf32-rounded)

__device__ __forceinline__ float to_tf32(float x) {
    uint32_t u;
    asm("cvt.rna.tf32.f32 %0, %1;" : "=r"(u) : "f"(x));
    return __uint_as_float(u);
}

// ------------------------------------------------ tf32 rounding of weights --
__global__ void cvt_kernel(const float* __restrict__ src, float* __restrict__ dst) {
    int i = blockIdx.x * 256 + threadIdx.x;
    float4 v = ((const float4*)src)[i];
    v.x = to_tf32(v.x); v.y = to_tf32(v.y); v.z = to_tf32(v.z); v.w = to_tf32(v.w);
    ((float4*)dst)[i] = v;
}

// --------------------------------------------------------------- layernorm --
__global__ void ln_kernel(const float* __restrict__ x,
                          const float* __restrict__ g,
                          const float* __restrict__ b) {
    int row = blockIdx.x;
    int tid = threadIdx.x;
    const float4* xr = (const float4*)(x + (size_t)row * D_MODEL);
    float4 v = xr[tid];
    float s  = v.x + v.y + v.z + v.w;
    float ss = v.x*v.x + v.y*v.y + v.z*v.z + v.w*v.w;
    #pragma unroll
    for (int o = 16; o; o >>= 1) {
        s  += __shfl_xor_sync(0xffffffffu, s,  o);
        ss += __shfl_xor_sync(0xffffffffu, ss, o);
    }
    __shared__ float sm[8], sm2[8];
    int w = tid >> 5, l = tid & 31;
    if (l == 0) { sm[w] = s; sm2[w] = ss; }
    __syncthreads();
    if (tid == 0) {
        float a = 0.f, a2 = 0.f;
        #pragma unroll
        for (int i = 0; i < 8; i++) { a += sm[i]; a2 += sm2[i]; }
        sm[0]  = a  * (1.0f / D_MODEL);
        sm2[0] = a2 * (1.0f / D_MODEL);
    }
    __syncthreads();
    float mu = sm[0];
    float var = sm2[0] - mu * mu;
    float rs = rsqrtf(var + 1e-5f);
    float4 gv = ((const float4*)g)[tid], bv = ((const float4*)b)[tid];
    float4 o;
    o.x = to_tf32((v.x - mu) * rs * gv.x + bv.x);
    o.y = to_tf32((v.y - mu) * rs * gv.y + bv.y);
    o.z = to_tf32((v.z - mu) * rs * gv.z + bv.z);
    o.w = to_tf32((v.w - mu) * rs * gv.w + bv.w);
    ((float4*)(g_xn + (size_t)row * D_MODEL))[tid] = o;
}

// ------------------------------------ causal dwconv + silu (8 rows/thread) --
__global__ void conv_silu_kernel(const float* __restrict__ cw,
                                 const float* __restrict__ cb) {
    int di4 = threadIdx.x;            // 0..255 channel group (4 ch each)
    int r0  = blockIdx.x * 8;         // row group; 2048 % 8 == 0 so same sequence
    int t0  = r0 & (SEQ_T - 1);
    const float4* w4 = (const float4*)cw + di4 * 4;
    float4 w0 = w4[0], w1 = w4[1], w2 = w4[2], w3 = w4[3];
    float4 bias = ((const float4*)cb)[di4];
    const float* basecol = g_xz + (size_t)di4 * 4;
    float4 zero = make_float4(0.f, 0.f, 0.f, 0.f);
    float4 hm3 = zero, hm2 = zero, hm1 = zero;
    if (t0 != 0) {
        hm3 = *(const float4*)(basecol + (size_t)(r0 - 3) * (2 * DIM));
        hm2 = *(const float4*)(basecol + (size_t)(r0 - 2) * (2 * DIM));
        hm1 = *(const float4*)(basecol + (size_t)(r0 - 1) * (2 * DIM));
    }
    #pragma unroll
    for (int i = 0; i < 8; i++) {
        int row = r0 + i;
        float4 cur = *(const float4*)(basecol + (size_t)row * (2 * DIM));
        float4 a;
        a.x = bias.x + w0.x*hm3.x + w0.y*hm2.x + w0.z*hm1.x + w0.w*cur.x;
        a.y = bias.y + w1.x*hm3.y + w1.y*hm2.y + w1.z*hm1.y + w1.w*cur.y;
        a.z = bias.z + w2.x*hm3.z + w2.y*hm2.z + w2.z*hm1.z + w2.w*cur.z;
        a.w = bias.w + w3.x*hm3.w + w3.y*hm2.w + w3.z*hm1.w + w3.w*cur.w;
        a.x = a.x / (1.f + __expf(-a.x));
        a.y = a.y / (1.f + __expf(-a.y));
        a.z = a.z / (1.f + __expf(-a.z));
        a.w = a.w / (1.f + __expf(-a.w));
        ((float4*)g_xc)[row * (DIM/4) + di4] = a;
        float4 at;
        at.x = to_tf32(a.x); at.y = to_tf32(a.y); at.z = to_tf32(a.z); at.w = to_tf32(a.w);
        ((float4*)g_xct)[row * (DIM/4) + di4] = at;
        hm3 = hm2; hm2 = hm1; hm1 = cur;
    }
}

// -------------------------------------------------------- [B_w|C_w] concat --
__global__ void bcw_kernel(const float* __restrict__ Bw,
                           const float* __restrict__ Cw) {
    int idx = blockIdx.x * 256 + threadIdx.x;   // DIM*32, layout [k][n]
    int j = idx & 31, k = idx >> 5;
    float v = (j < 16) ? Bw[k * 16 + j] : Cw[k * 16 + (j - 16)];
    g_bcw[idx] = to_tf32(v);
}

// ----------------------------------------------------- tf32 mma.sync GEMM ---
__device__ __forceinline__ void mma_tf32(float* c, const uint32_t* a, const uint32_t* b) {
    asm volatile(
        "mma.sync.aligned.m16n8k8.row.col.f32.tf32.tf32.f32 "
        "{%0,%1,%2,%3}, {%4,%5,%6,%7}, {%8,%9}, {%0,%1,%2,%3};\n"
        : "+f"(c[0]), "+f"(c[1]), "+f"(c[2]), "+f"(c[3])
        : "r"(a[0]), "r"(a[1]), "r"(a[2]), "r"(a[3]), "r"(b[0]), "r"(b[1]));
}

// EPI: 0 = plain, 1 = softplus(acc + bias[col]), 2 = acc + addend[row,col]
template<int EPI>
__device__ __forceinline__ float epi_apply(float v, int row, int col, int N,
                                           const float* bias, const float* addend) {
    if (EPI == 1) {
        float s = v + bias[col];
        return (s > 20.f) ? s : log1pf(__expf(s));
    }
    if (EPI == 2) return v + addend[(size_t)row * N + col];
    return v;
}

// 3-stage cp.async multistage GEMM. Inputs must already be tf32-rounded.
// Every mainloop iteration commits exactly one group (empty in the tail),
// so wait_group 1 always guarantees the next stage is resident.
template<int BM, int BN, int BK, int WM, int WN, int EPI>
__global__ void __launch_bounds__((BM/WM)*(BN/WN)*32)
gemm_kernel(const float* __restrict__ A, const float* __restrict__ Bg,
            float* __restrict__ Cg, int M, int N, int K,
            const float* __restrict__ bias, const float* __restrict__ addend)
{
    constexpr int WARPS_M = BM / WM;
    constexpr int WARPS_N = BN / WN;
    constexpr int NT = WARPS_M * WARPS_N * 32;
    constexpr int MD = WM / 16;
    constexpr int ND = WN / 8;
    static_assert(BK == 32, "BK must be 32");
    constexpr int AS = BK + 4;        // 36: bank-spread
    constexpr int BS = BN + 8;
    constexpr int STAGES = 3;
    constexpr int ASZ = BM * AS;
    constexpr int BSZ = BK * BS;
    constexpr int AV4 = BM * BK / 4;
    constexpr int APT = AV4 / NT;
    constexpr int BV4 = BK * BN / 4;
    constexpr int BPT = (BV4 + NT - 1) / NT;
    constexpr bool BFULL = (BV4 % NT) == 0;

    extern __shared__ float smem[];
    float* sAbase = smem;
    float* sBbase = smem + STAGES * ASZ;

    const int tid = threadIdx.x;
    const int bm = blockIdx.y * BM;
    const int bn = blockIdx.x * BN;
    const int warp = tid >> 5, lane = tid & 31;
    const int wm = (warp / WARPS_N) * WM;
    const int wn = (warp % WARPS_N) * WN;
    const int grp = lane >> 2, tg = lane & 3;
    const int KT = K / BK;

    float acc[MD][ND][4];
    #pragma unroll
    for (int i = 0; i < MD; i++)
        #pragma unroll
        for (int j = 0; j < ND; j++)
            #pragma unroll
            for (int e = 0; e < 4; e++) acc[i][j][e] = 0.f;

    auto issue = [&](int kt, int stage) {
        int k0 = kt * BK;
        float* sA = sAbase + stage * ASZ;
        float* sB = sBbase + stage * BSZ;
        #pragma unroll
        for (int i = 0; i < APT; i++) {
            int idx = tid + i * NT;
            int r = idx / (BK / 4), c4 = idx % (BK / 4);
            uint32_t dst = (uint32_t)__cvta_generic_to_shared(sA + r * AS + c4 * 4);
            const float* src = A + (size_t)(bm + r) * K + k0 + c4 * 4;
            asm volatile("cp.async.cg.shared.global [%0], [%1], 16;\n"
                         :: "r"(dst), "l"(src));
        }
        #pragma unroll
        for (int i = 0; i < BPT; i++) {
            int idx = tid + i * NT;
            if (BFULL || idx < BV4) {
                int r = idx / (BN / 4), c4 = idx % (BN / 4);
                uint32_t dst = (uint32_t)__cvta_generic_to_shared(sB + r * BS + c4 * 4);
                const float* src = Bg + (size_t)(k0 + r) * N + bn + c4 * 4;
                asm volatile("cp.async.cg.shared.global [%0], [%1], 16;\n"
                             :: "r"(dst), "l"(src));
            }
        }
        asm volatile("cp.async.commit_group;\n" ::: "memory");
    };

    issue(0, 0);
    issue(1, 1);
    asm volatile("cp.async.wait_group 1;\n" ::: "memory");
    __syncthreads();

    for (int kt = 0; kt < KT; kt++) {
        int stage = kt % STAGES;
        if (kt + 2 < KT) {
            issue(kt + 2, (kt + 2) % STAGES);
        } else {
            asm volatile("cp.async.commit_group;\n" ::: "memory");
        }
        const float* sA = sAbase + stage * ASZ;
        const float* sB = sBbase + stage * BSZ;
        #pragma unroll
        for (int ks = 0; ks < BK / 8; ks++) {
            uint32_t af[MD][4], bf[ND][2];
            #pragma unroll
            for (int md = 0; md < MD; md++) {
                const float* ap = sA + (wm + md * 16) * AS + ks * 8;
                af[md][0] = __float_as_uint(ap[ grp      * AS + tg    ]);
                af[md][1] = __float_as_uint(ap[(grp + 8) * AS + tg    ]);
                af[md][2] = __float_as_uint(ap[ grp      * AS + tg + 4]);
                af[md][3] = __float_as_uint(ap[(grp + 8) * AS + tg + 4]);
            }
            #pragma unroll
            for (int nd = 0; nd < ND; nd++) {
                const float* bp = sB + (ks * 8) * BS + wn + nd * 8 + grp;
                bf[nd][0] = __float_as_uint(bp[ tg      * BS]);
                bf[nd][1] = __float_as_uint(bp[(tg + 4) * BS]);
            }
            #pragma unroll
            for (int md = 0; md < MD; md++)
                #pragma unroll
                for (int nd = 0; nd < ND; nd++)
                    mma_tf32(acc[md][nd], af[md], bf[nd]);
        }
        asm volatile("cp.async.wait_group 1;\n" ::: "memory");
        __syncthreads();
    }

    // epilogue
    #pragma unroll
    for (int md = 0; md < MD; md++) {
        #pragma unroll
        for (int nd = 0; nd < ND; nd++) {
            int row0 = bm + wm + md * 16 + grp;
            int col  = bn + wn + nd * 8 + 2 * tg;
            float2 p;
            p.x = epi_apply<EPI>(acc[md][nd][0], row0, col,     N, bias, addend);
            p.y = epi_apply<EPI>(acc[md][nd][1], row0, col + 1, N, bias, addend);
            *(float2*)(Cg + (size_t)row0 * N + col) = p;
            float2 q;
            q.x = epi_apply<EPI>(acc[md][nd][2], row0 + 8, col,     N, bias, addend);
            q.y = epi_apply<EPI>(acc[md][nd][3], row0 + 8, col + 1, N, bias, addend);
            *(float2*)(Cg + (size_t)(row0 + 8) * N + col) = q;
        }
    }
}

// --------------------------------------------------------------- scan ------
__global__ void scanA_kernel(const float* __restrict__ logA) {
    int di = blockIdx.x * 128 + threadIdx.x;
    int c = blockIdx.y, b = blockIdx.z;
    float Av = -__expf(logA[di]);
    float h[DSTATE];
    #pragma unroll
    for (int s = 0; s < DSTATE; s++) h[s] = 0.f;
    float P = 1.f;
    int rbase = b * SEQ_T + c * TCHUNK;
    for (int t = 0; t < TCHUNK; t++) {
        int row = rbase + t;
        float dtv = g_dt[row * DIM + di];
        float xv  = g_xc[row * DIM + di];
        float decay = __expf(fminf(dtv * Av, 0.f));
        float u = dtv * xv;
        const float4* bc = (const float4*)(g_bc + row * 32);
        float4 b0 = bc[0], b1 = bc[1], b2 = bc[2], b3 = bc[3];
        float Bv[DSTATE] = {b0.x,b0.y,b0.z,b0.w, b1.x,b1.y,b1.z,b1.w,
                            b2.x,b2.y,b2.z,b2.w, b3.x,b3.y,b3.z,b3.w};
        P *= decay;
        #pragma unroll
        for (int s = 0; s < DSTATE; s++) h[s] = h[s] * decay + u * Bv[s];
    }
    int o = ((b * NCHUNK + c) * DSTATE) * DIM + di;
    #pragma unroll
    for (int s = 0; s < DSTATE; s++) g_hend[o + s * DIM] = h[s];
    g_Pp[(b * NCHUNK + c) * DIM + di] = P;
}

__global__ void combine_kernel() {
    int idx = blockIdx.x * 256 + threadIdx.x;   // NBATCH*DSTATE*DIM
    int di = idx % DIM;
    int s  = (idx / DIM) % DSTATE;
    int b  = idx / (DIM * DSTATE);
    float h = 0.f;
    g_hinit[((b * NCHUNK + 0) * DSTATE + s) * DIM + di] = 0.f;
    for (int c = 1; c < NCHUNK; c++) {
        float he = g_hend[((b * NCHUNK + c - 1) * DSTATE + s) * DIM + di];
        float Pv = g_Pp [ (b * NCHUNK + c - 1) * DIM + di];
        h = he + Pv * h;
        g_hinit[((b * NCHUNK + c) * DSTATE + s) * DIM + di] = h;
    }
}

__global__ void scanC_kernel(const float* __restrict__ logA,
                             const float* __restrict__ Dp) {
    int di = blockIdx.x * 128 + threadIdx.x;
    int c = blockIdx.y, b = blockIdx.z;
    float Av = -__expf(logA[di]);
    float Dv = Dp[di];
    float h[DSTATE];
    int o = ((b * NCHUNK + c) * DSTATE) * DIM + di;
    #pragma unroll
    for (int s = 0; s < DSTATE; s++) h[s] = g_hinit[o + s * DIM];
    int rbase = b * SEQ_T + c * TCHUNK;
    for (int t = 0; t < TCHUNK; t++) {
        int row = rbase + t;
        float dtv = g_dt[row * DIM + di];
        float xv  = g_xc[row * DIM + di];
        float decay = __expf(fminf(dtv * Av, 0.f));
        float u = dtv * xv;
        const float4* bc = (const float4*)(g_bc + row * 32);
        float4 b0 = bc[0], b1 = bc[1], b2 = bc[2], b3 = bc[3];
        float4 c0 = bc[4], c1 = bc[5], c2 = bc[6], c3 = bc[7];
        float Bv[DSTATE] = {b0.x,b0.y,b0.z,b0.w, b1.x,b1.y,b1.z,b1.w,
                            b2.x,b2.y,b2.z,b2.w, b3.x,b3.y,b3.z,b3.w};
        float Cv[DSTATE] = {c0.x,c0.y,c0.z,c0.w, c1.x,c1.y,c1.z,c1.w,
                            c2.x,c2.y,c2.z,c2.w, c3.x,c3.y,c3.z,c3.w};
        float y = 0.f;
        #pragma unroll
        for (int s = 0; s < DSTATE; s++) {
            h[s] = h[s] * decay + u * Bv[s];
            y += h[s] * Cv[s];
        }
        float zv = g_xz[row * (2 * DIM) + DIM + di];
        float sg = zv / (1.f + __expf(-zv));
        g_yg[row * DIM + di] = to_tf32((y + xv * Dv) * sg);
    }
}

// ----------------------------------------------------------------- launch ---
static inline int gemm_smem_bytes(int BM, int BN, int BK) {
    return 3 * (BM * (BK + 4) + BK * (BN + 8)) * (int)sizeof(float);
}

extern "C" void kernel_launch(void* const* d_in, const int* in_sizes, int n_in,
                              void* d_out, int out_size) {
    const float* x      = (const float*)d_in[0];
    const float* ln_g   = (const float*)d_in[1];
    const float* ln_b   = (const float*)d_in[2];
    const float* W_in   = (const float*)d_in[3];
    const float* conv_w = (const float*)d_in[4];
    const float* conv_b = (const float*)d_in[5];
    const float* dt_w   = (const float*)d_in[6];
    const float* dt_b   = (const float*)d_in[7];
    const float* B_w    = (const float*)d_in[8];
    const float* C_w    = (const float*)d_in[9];
    const float* log_A  = (const float*)d_in[10];
    const float* D_par  = (const float*)d_in[11];
    const float* W_out  = (const float*)d_in[12];
    float* out = (float*)d_out;

    float *p_xn, *p_xz, *p_xct, *p_dt, *p_bc, *p_bcw, *p_yg;
    float *p_w1t, *p_wdt, *p_wot;
    cudaGetSymbolAddress((void**)&p_xn,  g_xn);
    cudaGetSymbolAddress((void**)&p_xz,  g_xz);
    cudaGetSymbolAddress((void**)&p_xct, g_xct);
    cudaGetSymbolAddress((void**)&p_dt,  g_dt);
    cudaGetSymbolAddress((void**)&p_bc,  g_bc);
    cudaGetSymbolAddress((void**)&p_bcw, g_bcw);
    cudaGetSymbolAddress((void**)&p_yg,  g_yg);
    cudaGetSymbolAddress((void**)&p_w1t, g_w1t);
    cudaGetSymbolAddress((void**)&p_wdt, g_wdt);
    cudaGetSymbolAddress((void**)&p_wot, g_wot);

    int smem_big   = gemm_smem_bytes(128, 128, 32);   // 107,520 -> 2 CTAs/SM
    int smem_small = gemm_smem_bytes(64, 32, 32);
    cudaFuncSetAttribute(gemm_kernel<128,128,32,64,64,0>,
                         cudaFuncAttributeMaxDynamicSharedMemorySize, smem_big);
    cudaFuncSetAttribute(gemm_kernel<128,128,32,64,64,1>,
                         cudaFuncAttributeMaxDynamicSharedMemorySize, smem_big);
    cudaFuncSetAttribute(gemm_kernel<128,128,32,64,64,2>,
                         cudaFuncAttributeMaxDynamicSharedMemorySize, smem_big);
    cudaFuncSetAttribute(gemm_kernel<64,32,32,32,16,0>,
                         cudaFuncAttributeMaxDynamicSharedMemorySize, smem_small);

    // 0. tf32-round the GEMM weights
    cvt_kernel<<<(D_MODEL*2*DIM/4)/256, 256>>>(W_in,  p_w1t);
    cvt_kernel<<<(DIM*DIM/4)/256,       256>>>(dt_w,  p_wdt);
    cvt_kernel<<<(DIM*D_MODEL/4)/256,   256>>>(W_out, p_wot);
    bcw_kernel<<<DIM*32/256, 256>>>(B_w, C_w);

    // 1. layernorm (tf32-rounded output)
    ln_kernel<<<BT, 256>>>(x, ln_g, ln_b);

    // 2. xz = xn @ W_in   [4096 x 2048]   (4 warps/CTA, 64x64 warp tiles)
    gemm_kernel<128,128,32,64,64,0><<<dim3(2*DIM/128, BT/128), 128, smem_big>>>(
        p_xn, p_w1t, p_xz, BT, 2*DIM, D_MODEL, nullptr, nullptr);

    // 3. causal depthwise conv + silu (rolling window, 8 rows/thread)
    conv_silu_kernel<<<BT/8, 256>>>(conv_w, conv_b);

    // 4. dt = softplus(xct @ dt_w + dt_b)
    gemm_kernel<128,128,32,64,64,1><<<dim3(DIM/128, BT/128), 128, smem_big>>>(
        p_xct, p_wdt, p_dt, BT, DIM, DIM, dt_b, nullptr);

    // 5. [Bm|Cm] = xct @ [B_w|C_w]   [4096 x 32]
    gemm_kernel<64,32,32,32,16,0><<<dim3(1, BT/64), 128, smem_small>>>(
        p_xct, p_bcw, p_bc, BT, 32, DIM, nullptr, nullptr);

    // 6. chunked selective scan (exact; NCHUNK=64)
    scanA_kernel<<<dim3(DIM/128, NCHUNK, NBATCH), 128>>>(log_A);
    combine_kernel<<<NBATCH*DSTATE*DIM/256, 256>>>();
    scanC_kernel<<<dim3(DIM/128, NCHUNK, NBATCH), 128>>>(log_A, D_par);

    // 7. out = x + yg @ W_out
    gemm_kernel<128,128,32,64,64,2><<<dim3(DIM/128, BT/128), 128, smem_big>>>(
        p_yg, p_wot, out, BT, DIM, DIM, nullptr, x);
}

// round 15
// speedup vs baseline: 2.2707x; 1.4917x over previous
#include <cuda_runtime.h>
#include <cuda_fp16.h>
#include <cstdint>

#define D_MODEL 1024
#define DIM 1024
#define DSTATE 16
#define SEQ_T 2048
#define NBATCH 2
#define BT (NBATCH*SEQ_T)      // 4096 rows
#define NCHUNK 64
#define TCHUNK (SEQ_T/NCHUNK)  // 32

// ------------------------- scratch (static device globals; no allocation) ---
__device__ __half g_xnh [BT*D_MODEL];       // layernorm out (fp16)
__device__ float  g_xz  [BT*2*DIM];         // xn @ W_in (fp32)
__device__ float  g_xc  [BT*DIM];           // silu(conv) fp32 (scan input)
__device__ __half g_xch [BT*DIM];           // same, fp16 (GEMM input)
__device__ float  g_dt  [BT*DIM];
__device__ float  g_bc  [BT*32];            // [Bm | Cm]
__device__ __half g_bcwh[32*DIM];           // [B_w|C_w]^T  [32][1024] fp16
__device__ __half g_w1t [2*DIM*D_MODEL];    // W_in^T  [2048][1024] fp16
__device__ __half g_wdt [DIM*DIM];          // dt_w^T  fp16
__device__ __half g_wot [DIM*D_MODEL];      // W_out^T fp16
__device__ float  g_hend [NBATCH*NCHUNK*DSTATE*DIM];
__device__ float  g_Pp   [NBATCH*NCHUNK*DIM];
__device__ float  g_hinit[NBATCH*NCHUNK*DSTATE*DIM];
__device__ __half g_ygh [BT*DIM];           // gated scan output (fp16)

__device__ __forceinline__ uint32_t h2_as_u32(__half2 h) {
    union { __half2 h; uint32_t u; } cvt;
    cvt.h = h;
    return cvt.u;
}

// ------------------------------------------- weight transpose + fp16 round --
__global__ void transpose_h_kernel(const float* __restrict__ in, __half* __restrict__ out,
                                   int R, int C) {        // in [R,C] fp32 -> out [C,R] fp16
    __shared__ float tile[32][33];
    int bx = blockIdx.x * 32, by = blockIdx.y * 32;
    int tx = threadIdx.x, ty = threadIdx.y;
    #pragma unroll
    for (int j = 0; j < 32; j += 8)
        tile[ty + j][tx] = in[(size_t)(by + ty + j) * C + bx + tx];
    __syncthreads();
    #pragma unroll
    for (int j = 0; j < 32; j += 8)
        out[(size_t)(bx + ty + j) * R + by + tx] = __float2half_rn(tile[tx][ty + j]);
}

// [B_w|C_w]^T concat -> [32][1024] fp16
__global__ void bcw_kernel(const float* __restrict__ Bw, const float* __restrict__ Cw) {
    int idx = blockIdx.x * 256 + threadIdx.x;   // 32*1024
    int n = idx >> 10, k = idx & 1023;
    float v = (n < 16) ? Bw[k * 16 + n] : Cw[k * 16 + (n - 16)];
    g_bcwh[idx] = __float2half_rn(v);
}

// --------------------------------------------------------------- layernorm --
__global__ void ln_kernel(const float* __restrict__ x,
                          const float* __restrict__ g,
                          const float* __restrict__ b) {
    int row = blockIdx.x;
    int tid = threadIdx.x;
    const float4* xr = (const float4*)(x + (size_t)row * D_MODEL);
    float4 v = xr[tid];
    float s  = v.x + v.y + v.z + v.w;
    float ss = v.x*v.x + v.y*v.y + v.z*v.z + v.w*v.w;
    #pragma unroll
    for (int o = 16; o; o >>= 1) {
        s  += __shfl_xor_sync(0xffffffffu, s,  o);
        ss += __shfl_xor_sync(0xffffffffu, ss, o);
    }
    __shared__ float sm[8], sm2[8];
    int w = tid >> 5, l = tid & 31;
    if (l == 0) { sm[w] = s; sm2[w] = ss; }
    __syncthreads();
    if (tid == 0) {
        float a = 0.f, a2 = 0.f;
        #pragma unroll
        for (int i = 0; i < 8; i++) { a += sm[i]; a2 += sm2[i]; }
        sm[0]  = a  * (1.0f / D_MODEL);
        sm2[0] = a2 * (1.0f / D_MODEL);
    }
    __syncthreads();
    float mu = sm[0];
    float var = sm2[0] - mu * mu;
    float rs = rsqrtf(var + 1e-5f);
    float4 gv = ((const float4*)g)[tid], bv = ((const float4*)b)[tid];
    __half2 h0 = __floats2half2_rn((v.x - mu) * rs * gv.x + bv.x,
                                   (v.y - mu) * rs * gv.y + bv.y);
    __half2 h1 = __floats2half2_rn((v.z - mu) * rs * gv.z + bv.z,
                                   (v.w - mu) * rs * gv.w + bv.w);
    uint2 pk = make_uint2(h2_as_u32(h0), h2_as_u32(h1));
    ((uint2*)(g_xnh + (size_t)row * D_MODEL))[tid] = pk;
}

// ------------------------------------ causal dwconv + silu (8 rows/thread) --
__global__ void conv_silu_kernel(const float* __restrict__ cw,
                                 const float* __restrict__ cb) {
    int di4 = threadIdx.x;            // 0..255 channel group (4 ch each)
    int r0  = blockIdx.x * 8;         // row group; 2048 % 8 == 0 so same sequence
    int t0  = r0 & (SEQ_T - 1);
    const float4* w4 = (const float4*)cw + di4 * 4;
    float4 w0 = w4[0], w1 = w4[1], w2 = w4[2], w3 = w4[3];
    float4 bias = ((const float4*)cb)[di4];
    const float* basecol = g_xz + (size_t)di4 * 4;
    float4 zero = make_float4(0.f, 0.f, 0.f, 0.f);
    float4 hm3 = zero, hm2 = zero, hm1 = zero;
    if (t0 != 0) {
        hm3 = *(const float4*)(basecol + (size_t)(r0 - 3) * (2 * DIM));
        hm2 = *(const float4*)(basecol + (size_t)(r0 - 2) * (2 * DIM));
        hm1 = *(const float4*)(basecol + (size_t)(r0 - 1) * (2 * DIM));
    }
    #pragma unroll
    for (int i = 0; i < 8; i++) {
        int row = r0 + i;
        float4 cur = *(const float4*)(basecol + (size_t)row * (2 * DIM));
        float4 a;
        a.x = bias.x + w0.x*hm3.x + w0.y*hm2.x + w0.z*hm1.x + w0.w*cur.x;
        a.y = bias.y + w1.x*hm3.y + w1.y*hm2.y + w1.z*hm1.y + w1.w*cur.y;
        a.z = bias.z + w2.x*hm3.z + w2.y*hm2.z + w2.z*hm1.z + w2.w*cur.z;
        a.w = bias.w + w3.x*hm3.w + w3.y*hm2.w + w3.z*hm1.w + w3.w*cur.w;
        a.x = a.x / (1.f + __expf(-a.x));
        a.y = a.y / (1.f + __expf(-a.y));
        a.z = a.z / (1.f + __expf(-a.z));
        a.w = a.w / (1.f + __expf(-a.w));
        ((float4*)g_xc)[row * (DIM/4) + di4] = a;
        __half2 h0 = __floats2half2_rn(a.x, a.y);
        __half2 h1 = __floats2half2_rn(a.z, a.w);
        uint2 pk = make_uint2(h2_as_u32(h0), h2_as_u32(h1));
        ((uint2*)g_xch)[row * (DIM/4) + di4] = pk;
        hm3 = hm2; hm2 = hm1; hm1 = cur;
    }
}

// ------------------------------------------------------ fp16 mma.sync GEMM --
__device__ __forceinline__ void mma_f16(float* c, const uint32_t* a, const uint32_t* b) {
    asm volatile(
        "mma.sync.aligned.m16n8k16.row.col.f32.f16.f16.f32 "
        "{%0,%1,%2,%3}, {%4,%5,%6,%7}, {%8,%9}, {%0,%1,%2,%3};\n"
        : "+f"(c[0]), "+f"(c[1]), "+f"(c[2]), "+f"(c[3])
        : "r"(a[0]), "r"(a[1]), "r"(a[2]), "r"(a[3]), "r"(b[0]), "r"(b[1]));
}

// EPI: 0 = plain, 1 = softplus(acc + bias[col]), 2 = acc + addend[row,col]
template<int EPI>
__device__ __forceinline__ float epi_apply(float v, int row, int col, int N,
                                           const float* bias, const float* addend) {
    if (EPI == 1) {
        float s = v + bias[col];
        return (s > 20.f) ? s : log1pf(__expf(s));
    }
    if (EPI == 2) return v + addend[(size_t)row * N + col];
    return v;
}

// 3-stage cp.async multistage fp16 GEMM.
// A: [M][K] row-major fp16.  Bt: [N][K] row-major fp16 (pre-transposed weight).
// Uniform commit-group discipline: every iteration commits exactly one group.
template<int BM, int BN, int BK, int WM, int WN, int EPI>
__global__ void __launch_bounds__((BM/WM)*(BN/WN)*32)
hgemm_kernel(const __half* __restrict__ A, const __half* __restrict__ Bt,
             float* __restrict__ Cg, int M, int N, int K,
             const float* __restrict__ bias, const float* __restrict__ addend)
{
    constexpr int WARPS_M = BM / WM;
    constexpr int WARPS_N = BN / WN;
    constexpr int NT = WARPS_M * WARPS_N * 32;
    constexpr int MD = WM / 16;
    constexpr int ND = WN / 8;
    static_assert(BK % 16 == 0, "BK multiple of 16");
    constexpr int AS = BK + 8;        // halves; +8 keeps fragment LDS conflict-free
    constexpr int BS = BK + 8;
    constexpr int STAGES = 3;
    constexpr int ASZ = BM * AS;      // halves
    constexpr int BSZ = BN * BS;
    constexpr int ACH = BM * BK / 8;  // 16B chunks
    constexpr int APT = ACH / NT;
    constexpr int BCH = BN * BK / 8;
    constexpr int BPT = (BCH + NT - 1) / NT;
    constexpr bool BFULL = (BCH % NT) == 0;

    extern __shared__ __half smem[];
    __half* sAbase = smem;
    __half* sBbase = smem + STAGES * ASZ;

    const int tid = threadIdx.x;
    const int bm = blockIdx.y * BM;
    const int bn = blockIdx.x * BN;
    const int warp = tid >> 5, lane = tid & 31;
    const int wm = (warp / WARPS_N) * WM;
    const int wn = (warp % WARPS_N) * WN;
    const int grp = lane >> 2, tg = lane & 3;
    const int KT = K / BK;

    float acc[MD][ND][4];
    #pragma unroll
    for (int i = 0; i < MD; i++)
        #pragma unroll
        for (int j = 0; j < ND; j++)
            #pragma unroll
            for (int e = 0; e < 4; e++) acc[i][j][e] = 0.f;

    auto issue = [&](int kt, int stage) {
        int k0 = kt * BK;
        __half* sA = sAbase + stage * ASZ;
        __half* sB = sBbase + stage * BSZ;
        #pragma unroll
        for (int i = 0; i < APT; i++) {
            int idx = tid + i * NT;
            int r = idx / (BK / 8), c8 = idx % (BK / 8);
            uint32_t dst = (uint32_t)__cvta_generic_to_shared(sA + r * AS + c8 * 8);
            const __half* src = A + (size_t)(bm + r) * K + k0 + c8 * 8;
            asm volatile("cp.async.cg.shared.global [%0], [%1], 16;\n"
                         :: "r"(dst), "l"(src));
        }
        #pragma unroll
        for (int i = 0; i < BPT; i++) {
            int idx = tid + i * NT;
            if (BFULL || idx < BCH) {
                int r = idx / (BK / 8), c8 = idx % (BK / 8);
                uint32_t dst = (uint32_t)__cvta_generic_to_shared(sB + r * BS + c8 * 8);
                const __half* src = Bt + (size_t)(bn + r) * K + k0 + c8 * 8;
                asm volatile("cp.async.cg.shared.global [%0], [%1], 16;\n"
                             :: "r"(dst), "l"(src));
            }
        }
        asm volatile("cp.async.commit_group;\n" ::: "memory");
    };

    issue(0, 0);
    issue(1, 1);
    asm volatile("cp.async.wait_group 1;\n" ::: "memory");
    __syncthreads();

    for (int kt = 0; kt < KT; kt++) {
        int stage = kt % STAGES;
        if (kt + 2 < KT) {
            issue(kt + 2, (kt + 2) % STAGES);
        } else {
            asm volatile("cp.async.commit_group;\n" ::: "memory");
        }
        const __half* sA = sAbase + stage * ASZ;
        const __half* sB = sBbase + stage * BSZ;
        #pragma unroll
        for (int ks = 0; ks < BK / 16; ks++) {
            uint32_t af[MD][4], bf[ND][2];
            #pragma unroll
            for (int md = 0; md < MD; md++) {
                const __half* ap = sA + (wm + md * 16 + grp) * AS + ks * 16 + 2 * tg;
                af[md][0] = *(const uint32_t*)(ap);
                af[md][1] = *(const uint32_t*)(ap + 8 * AS);
                af[md][2] = *(const uint32_t*)(ap + 8);
                af[md][3] = *(const uint32_t*)(ap + 8 * AS + 8);
            }
            #pragma unroll
            for (int nd = 0; nd < ND; nd++) {
                const __half* bp = sB + (wn + nd * 8 + grp) * BS + ks * 16 + 2 * tg;
                bf[nd][0] = *(const uint32_t*)(bp);
                bf[nd][1] = *(const uint32_t*)(bp + 8);
            }
            #pragma unroll
            for (int md = 0; md < MD; md++)
                #pragma unroll
                for (int nd = 0; nd < ND; nd++)
                    mma_f16(acc[md][nd], af[md], bf[nd]);
        }
        asm volatile("cp.async.wait_group 1;\n" ::: "memory");
        __syncthreads();
    }

    // epilogue
    #pragma unroll
    for (int md = 0; md < MD; md++) {
        #pragma unroll
        for (int nd = 0; nd < ND; nd++) {
            int row0 = bm + wm + md * 16 + grp;
            int col  = bn + wn + nd * 8 + 2 * tg;
            float2 p;
            p.x = epi_apply<EPI>(acc[md][nd][0], row0, col,     N, bias, addend);
            p.y = epi_apply<EPI>(acc[md][nd][1], row0, col + 1, N, bias, addend);
            *(float2*)(Cg + (size_t)row0 * N + col) = p;
            float2 q;
            q.x = epi_apply<EPI>(acc[md][nd][2], row0 + 8, col,     N, bias, addend);
            q.y = epi_apply<EPI>(acc[md][nd][3], row0 + 8, col + 1, N, bias, addend);
            *(float2*)(Cg + (size_t)(row0 + 8) * N + col) = q;
        }
    }
}

// --------------------------------------------------------------- scan ------
__global__ void scanA_kernel(const float* __restrict__ logA) {
    int di = blockIdx.x * 128 + threadIdx.x;
    int c = blockIdx.y, b = blockIdx.z;
    float Av = -__expf(logA[di]);
    float h[DSTATE];
    #pragma unroll
    for (int s = 0; s < DSTATE; s++) h[s] = 0.f;
    float P = 1.f;
    int rbase = b * SEQ_T + c * TCHUNK;
    for (int t = 0; t < TCHUNK; t++) {
        int row = rbase + t;
        float dtv = g_dt[row * DIM + di];
        float xv  = g_xc[row * DIM + di];
        float decay = __expf(fminf(dtv * Av, 0.f));
        float u = dtv * xv;
        const float4* bc = (const float4*)(g_bc + row * 32);
        float4 b0 = bc[0], b1 = bc[1], b2 = bc[2], b3 = bc[3];
        float Bv[DSTATE] = {b0.x,b0.y,b0.z,b0.w, b1.x,b1.y,b1.z,b1.w,
                            b2.x,b2.y,b2.z,b2.w, b3.x,b3.y,b3.z,b3.w};
        P *= decay;
        #pragma unroll
        for (int s = 0; s < DSTATE; s++) h[s] = h[s] * decay + u * Bv[s];
    }
    int o = ((b * NCHUNK + c) * DSTATE) * DIM + di;
    #pragma unroll
    for (int s = 0; s < DSTATE; s++) g_hend[o + s * DIM] = h[s];
    g_Pp[(b * NCHUNK + c) * DIM + di] = P;
}

__global__ void combine_kernel() {
    int idx = blockIdx.x * 256 + threadIdx.x;   // NBATCH*DSTATE*DIM
    int di = idx % DIM;
    int s  = (idx / DIM) % DSTATE;
    int b  = idx / (DIM * DSTATE);
    float h = 0.f;
    g_hinit[((b * NCHUNK + 0) * DSTATE + s) * DIM + di] = 0.f;
    for (int c = 1; c < NCHUNK; c++) {
        float he = g_hend[((b * NCHUNK + c - 1) * DSTATE + s) * DIM + di];
        float Pv = g_Pp [ (b * NCHUNK + c - 1) * DIM + di];
        h = he + Pv * h;
        g_hinit[((b * NCHUNK + c) * DSTATE + s) * DIM + di] = h;
    }
}

__global__ void scanC_kernel(const float* __restrict__ logA,
                             const float* __restrict__ Dp) {
    int di = blockIdx.x * 128 + threadIdx.x;
    int c = blockIdx.y, b = blockIdx.z;
    float Av = -__expf(logA[di]);
    float Dv = Dp[di];
    float h[DSTATE];
    int o = ((b * NCHUNK + c) * DSTATE) * DIM + di;
    #pragma unroll
    for (int s = 0; s < DSTATE; s++) h[s] = g_hinit[o + s * DIM];
    int rbase = b * SEQ_T + c * TCHUNK;
    for (int t = 0; t < TCHUNK; t++) {
        int row = rbase + t;
        float dtv = g_dt[row * DIM + di];
        float xv  = g_xc[row * DIM + di];
        float decay = __expf(fminf(dtv * Av, 0.f));
        float u = dtv * xv;
        const float4* bc = (const float4*)(g_bc + row * 32);
        float4 b0 = bc[0], b1 = bc[1], b2 = bc[2], b3 = bc[3];
        float4 c0 = bc[4], c1 = bc[5], c2 = bc[6], c3 = bc[7];
        float Bv[DSTATE] = {b0.x,b0.y,b0.z,b0.w, b1.x,b1.y,b1.z,b1.w,
                            b2.x,b2.y,b2.z,b2.w, b3.x,b3.y,b3.z,b3.w};
        float Cv[DSTATE] = {c0.x,c0.y,c0.z,c0.w, c1.x,c1.y,c1.z,c1.w,
                            c2.x,c2.y,c2.z,c2.w, c3.x,c3.y,c3.z,c3.w};
        float y = 0.f;
        #pragma unroll
        for (int s = 0; s < DSTATE; s++) {
            h[s] = h[s] * decay + u * Bv[s];
            y += h[s] * Cv[s];
        }
        float zv = g_xz[row * (2 * DIM) + DIM + di];
        float sg = zv / (1.f + __expf(-zv));
        g_ygh[row * DIM + di] = __float2half_rn((y + xv * Dv) * sg);
    }
}

// ----------------------------------------------------------------- launch ---
static inline int hgemm_smem_bytes(int BM, int BN, int BK) {
    return 3 * (BM * (BK + 8) + BN * (BK + 8)) * 2;
}

extern "C" void kernel_launch(void* const* d_in, const int* in_sizes, int n_in,
                              void* d_out, int out_size) {
    const float* x      = (const float*)d_in[0];
    const float* ln_g   = (const float*)d_in[1];
    const float* ln_b   = (const float*)d_in[2];
    const float* W_in   = (const float*)d_in[3];
    const float* conv_w = (const float*)d_in[4];
    const float* conv_b = (const float*)d_in[5];
    const float* dt_w   = (const float*)d_in[6];
    const float* dt_b   = (const float*)d_in[7];
    const float* B_w    = (const float*)d_in[8];
    const float* C_w    = (const float*)d_in[9];
    const float* log_A  = (const float*)d_in[10];
    const float* D_par  = (const float*)d_in[11];
    const float* W_out  = (const float*)d_in[12];
    float* out = (float*)d_out;

    __half *p_xnh, *p_xch, *p_bcwh, *p_ygh, *p_w1t, *p_wdt, *p_wot;
    float *p_xz, *p_dt, *p_bc;
    cudaGetSymbolAddress((void**)&p_xnh,  g_xnh);
    cudaGetSymbolAddress((void**)&p_xz,   g_xz);
    cudaGetSymbolAddress((void**)&p_xch,  g_xch);
    cudaGetSymbolAddress((void**)&p_dt,   g_dt);
    cudaGetSymbolAddress((void**)&p_bc,   g_bc);
    cudaGetSymbolAddress((void**)&p_bcwh, g_bcwh);
    cudaGetSymbolAddress((void**)&p_ygh,  g_ygh);
    cudaGetSymbolAddress((void**)&p_w1t,  g_w1t);
    cudaGetSymbolAddress((void**)&p_wdt,  g_wdt);
    cudaGetSymbolAddress((void**)&p_wot,  g_wot);

    int smem_big   = hgemm_smem_bytes(128, 128, 64);   // 110,592 B
    int smem_small = hgemm_smem_bytes(64, 32, 64);     //  41,472 B
    cudaFuncSetAttribute(hgemm_kernel<128,128,64,64,64,0>,
                         cudaFuncAttributeMaxDynamicSharedMemorySize, smem_big);
    cudaFuncSetAttribute(hgemm_kernel<128,128,64,64,64,1>,
                         cudaFuncAttributeMaxDynamicSharedMemorySize, smem_big);
    cudaFuncSetAttribute(hgemm_kernel<128,128,64,64,64,2>,
                         cudaFuncAttributeMaxDynamicSharedMemorySize, smem_big);
    cudaFuncSetAttribute(hgemm_kernel<64,32,64,32,16,0>,
                         cudaFuncAttributeMaxDynamicSharedMemorySize, smem_small);

    // 0. weight transposes -> [N][K] fp16
    transpose_h_kernel<<<dim3(2*DIM/32, D_MODEL/32), dim3(32,8)>>>(W_in,  p_w1t, D_MODEL, 2*DIM);
    transpose_h_kernel<<<dim3(DIM/32,   DIM/32),     dim3(32,8)>>>(dt_w,  p_wdt, DIM, DIM);
    transpose_h_kernel<<<dim3(DIM/32,   DIM/32),     dim3(32,8)>>>(W_out, p_wot, DIM, DIM);
    bcw_kernel<<<32*DIM/256, 256>>>(B_w, C_w);

    // 1. layernorm (fp16 output)
    ln_kernel<<<BT, 256>>>(x, ln_g, ln_b);

    // 2. xz = xn @ W_in   [4096 x 2048]
    hgemm_kernel<128,128,64,64,64,0><<<dim3(2*DIM/128, BT/128), 128, smem_big>>>(
        p_xnh, p_w1t, p_xz, BT, 2*DIM, D_MODEL, nullptr, nullptr);

    // 3. causal depthwise conv + silu (fp32 + fp16 copies)
    conv_silu_kernel<<<BT/8, 256>>>(conv_w, conv_b);

    // 4. dt = softplus(xch @ dt_w + dt_b)
    hgemm_kernel<128,128,64,64,64,1><<<dim3(DIM/128, BT/128), 128, smem_big>>>(
        p_xch, p_wdt, p_dt, BT, DIM, DIM, dt_b, nullptr);

    // 5. [Bm|Cm] = xch @ [B_w|C_w]   [4096 x 32]
    hgemm_kernel<64,32,64,32,16,0><<<dim3(1, BT/64), 128, smem_small>>>(
        p_xch, p_bcwh, p_bc, BT, 32, DIM, nullptr, nullptr);

    // 6. chunked selective scan (exact; NCHUNK=64)
    scanA_kernel<<<dim3(DIM/128, NCHUNK, NBATCH), 128>>>(log_A);
    combine_kernel<<<NBATCH*DSTATE*DIM/256, 256>>>();
    scanC_kernel<<<dim3(DIM/128, NCHUNK, NBATCH), 128>>>(log_A, D_par);

    // 7. out = x + yg @ W_out
    hgemm_kernel<128,128,64,64,64,2><<<dim3(DIM/128, BT/128), 128, smem_big>>>(
        p_ygh, p_wot, out, BT, DIM, DIM, nullptr, x);
}

// round 17
// speedup vs baseline: 2.4319x; 1.0710x over previous
#include <cuda_runtime.h>
#include <cuda_fp16.h>
#include <cstdint>

#define D_MODEL 1024
#define DIM 1024
#define DSTATE 16
#define SEQ_T 2048
#define NBATCH 2
#define BT (NBATCH*SEQ_T)      // 4096 rows
#define NCHUNK 64
#define TCHUNK (SEQ_T/NCHUNK)  // 32

// ------------------------- scratch (static device globals; no allocation) ---
__device__ __half g_xnh [BT*D_MODEL];       // layernorm out (fp16)
__device__ float  g_xz  [BT*2*DIM];         // xn @ W_in (fp32)
__device__ float  g_xc  [BT*DIM];           // silu(conv) fp32 (scan input)
__device__ __half g_xch [BT*DIM];           // same, fp16 (GEMM input)
__device__ float  g_dt  [BT*DIM];
__device__ float  g_bc  [BT*32];            // [Bm | Cm]
__device__ __half g_bcwh[32*DIM];           // [B_w|C_w]^T  [32][1024] fp16
__device__ __half g_w1t [2*DIM*D_MODEL];    // W_in^T  [2048][1024] fp16
__device__ __half g_wdt [DIM*DIM];          // dt_w^T  fp16
__device__ __half g_wot [DIM*D_MODEL];      // W_out^T fp16
__device__ float  g_hend [NBATCH*NCHUNK*DSTATE*DIM];
__device__ float  g_Pp   [NBATCH*NCHUNK*DIM];
__device__ float  g_hinit[NBATCH*NCHUNK*DSTATE*DIM];
__device__ __half g_ygh [BT*DIM];           // gated scan output (fp16)

__device__ __forceinline__ uint32_t h2_as_u32(__half2 h) {
    union { __half2 h; uint32_t u; } cvt;
    cvt.h = h;
    return cvt.u;
}
__device__ __forceinline__ void ldsm4(uint32_t& r0, uint32_t& r1, uint32_t& r2,
                                      uint32_t& r3, uint32_t addr) {
    asm volatile("ldmatrix.sync.aligned.m8n8.x4.shared.b16 {%0,%1,%2,%3}, [%4];"
                 : "=r"(r0), "=r"(r1), "=r"(r2), "=r"(r3) : "r"(addr));
}

// ---------------------- fused prep: 3 weight transposes + [B|C]^T concat ----
__device__ __forceinline__ void tr_tile(const float* __restrict__ in,
                                        __half* __restrict__ out,
                                        int R, int C, int bx, int by,
                                        int tx, int ty, float tile[32][33]) {
    #pragma unroll
    for (int j = 0; j < 32; j += 8)
        tile[ty + j][tx] = in[(size_t)(by * 32 + ty + j) * C + bx * 32 + tx];
    __syncthreads();
    #pragma unroll
    for (int j = 0; j < 32; j += 8)
        out[(size_t)(bx * 32 + ty + j) * R + by * 32 + tx] =
            __float2half_rn(tile[tx][ty + j]);
}

__global__ void prep_kernel(const float* __restrict__ W_in,
                            const float* __restrict__ dt_w,
                            const float* __restrict__ W_out,
                            const float* __restrict__ Bw,
                            const float* __restrict__ Cw) {
    __shared__ float tile[32][33];
    int bid = blockIdx.x;
    int tx = threadIdx.x, ty = threadIdx.y;
    if (bid < 2048) {                       // W_in [1024,2048] -> [2048][1024]
        tr_tile(W_in, g_w1t, D_MODEL, 2*DIM, bid % 64, bid / 64, tx, ty, tile);
    } else if (bid < 3072) {                // dt_w [1024,1024]
        int b = bid - 2048;
        tr_tile(dt_w, g_wdt, DIM, DIM, b % 32, b / 32, tx, ty, tile);
    } else if (bid < 4096) {                // W_out [1024,1024]
        int b = bid - 3072;
        tr_tile(W_out, g_wot, DIM, DIM, b % 32, b / 32, tx, ty, tile);
    } else {                                // bcw concat: 32*1024 elems
        int idx = (bid - 4096) * 256 + ty * 32 + tx;
        int n = idx >> 10, k = idx & 1023;
        float v = (n < 16) ? Bw[k * 16 + n] : Cw[k * 16 + (n - 16)];
        g_bcwh[idx] = __float2half_rn(v);
    }
}

// --------------------------------------------------------------- layernorm --
__global__ void ln_kernel(const float* __restrict__ x,
                          const float* __restrict__ g,
                          const float* __restrict__ b) {
    int row = blockIdx.x;
    int tid = threadIdx.x;
    const float4* xr = (const float4*)(x + (size_t)row * D_MODEL);
    float4 v = xr[tid];
    float s  = v.x + v.y + v.z + v.w;
    float ss = v.x*v.x + v.y*v.y + v.z*v.z + v.w*v.w;
    #pragma unroll
    for (int o = 16; o; o >>= 1) {
        s  += __shfl_xor_sync(0xffffffffu, s,  o);
        ss += __shfl_xor_sync(0xffffffffu, ss, o);
    }
    __shared__ float sm[8], sm2[8];
    int w = tid >> 5, l = tid & 31;
    if (l == 0) { sm[w] = s; sm2[w] = ss; }
    __syncthreads();
    if (tid == 0) {
        float a = 0.f, a2 = 0.f;
        #pragma unroll
        for (int i = 0; i < 8; i++) { a += sm[i]; a2 += sm2[i]; }
        sm[0]  = a  * (1.0f / D_MODEL);
        sm2[0] = a2 * (1.0f / D_MODEL);
    }
    __syncthreads();
    float mu = sm[0];
    float var = sm2[0] - mu * mu;
    float rs = rsqrtf(var + 1e-5f);
    float4 gv = ((const float4*)g)[tid], bv = ((const float4*)b)[tid];
    __half2 h0 = __floats2half2_rn((v.x - mu) * rs * gv.x + bv.x,
                                   (v.y - mu) * rs * gv.y + bv.y);
    __half2 h1 = __floats2half2_rn((v.z - mu) * rs * gv.z + bv.z,
                                   (v.w - mu) * rs * gv.w + bv.w);
    uint2 pk = make_uint2(h2_as_u32(h0), h2_as_u32(h1));
    ((uint2*)(g_xnh + (size_t)row * D_MODEL))[tid] = pk;
}

// ------------------------------------ causal dwconv + silu (8 rows/thread) --
__global__ void conv_silu_kernel(const float* __restrict__ cw,
                                 const float* __restrict__ cb) {
    int di4 = threadIdx.x;            // 0..255 channel group (4 ch each)
    int r0  = blockIdx.x * 8;
    int t0  = r0 & (SEQ_T - 1);
    const float4* w4 = (const float4*)cw + di4 * 4;
    float4 w0 = w4[0], w1 = w4[1], w2 = w4[2], w3 = w4[3];
    float4 bias = ((const float4*)cb)[di4];
    const float* basecol = g_xz + (size_t)di4 * 4;
    float4 zero = make_float4(0.f, 0.f, 0.f, 0.f);
    float4 hm3 = zero, hm2 = zero, hm1 = zero;
    if (t0 != 0) {
        hm3 = *(const float4*)(basecol + (size_t)(r0 - 3) * (2 * DIM));
        hm2 = *(const float4*)(basecol + (size_t)(r0 - 2) * (2 * DIM));
        hm1 = *(const float4*)(basecol + (size_t)(r0 - 1) * (2 * DIM));
    }
    #pragma unroll
    for (int i = 0; i < 8; i++) {
        int row = r0 + i;
        float4 cur = *(const float4*)(basecol + (size_t)row * (2 * DIM));
        float4 a;
        a.x = bias.x + w0.x*hm3.x + w0.y*hm2.x + w0.z*hm1.x + w0.w*cur.x;
        a.y = bias.y + w1.x*hm3.y + w1.y*hm2.y + w1.z*hm1.y + w1.w*cur.y;
        a.z = bias.z + w2.x*hm3.z + w2.y*hm2.z + w2.z*hm1.z + w2.w*cur.z;
        a.w = bias.w + w3.x*hm3.w + w3.y*hm2.w + w3.z*hm1.w + w3.w*cur.w;
        a.x = a.x / (1.f + __expf(-a.x));
        a.y = a.y / (1.f + __expf(-a.y));
        a.z = a.z / (1.f + __expf(-a.z));
        a.w = a.w / (1.f + __expf(-a.w));
        ((float4*)g_xc)[row * (DIM/4) + di4] = a;
        __half2 h0 = __floats2half2_rn(a.x, a.y);
        __half2 h1 = __floats2half2_rn(a.z, a.w);
        uint2 pk = make_uint2(h2_as_u32(h0), h2_as_u32(h1));
        ((uint2*)g_xch)[row * (DIM/4) + di4] = pk;
        hm3 = hm2; hm2 = hm1; hm1 = cur;
    }
}

// ------------------------------------------------------ fp16 mma.sync GEMM --
__device__ __forceinline__ void mma_f16(float* c, const uint32_t* a, const uint32_t* b) {
    asm volatile(
        "mma.sync.aligned.m16n8k16.row.col.f32.f16.f16.f32 "
        "{%0,%1,%2,%3}, {%4,%5,%6,%7}, {%8,%9}, {%0,%1,%2,%3};\n"
        : "+f"(c[0]), "+f"(c[1]), "+f"(c[2]), "+f"(c[3])
        : "r"(a[0]), "r"(a[1]), "r"(a[2]), "r"(a[3]), "r"(b[0]), "r"(b[1]));
}

// EPI: 0 = plain, 1 = softplus(acc + bias[col]), 2 = acc + addend[row,col]
template<int EPI>
__device__ __forceinline__ float epi_apply(float v, int row, int col, int N,
                                           const float* bias, const float* addend) {
    if (EPI == 1) {
        float s = v + bias[col];
        return (s > 20.f) ? s : log1pf(__expf(s));
    }
    if (EPI == 2) return v + addend[(size_t)row * N + col];
    return v;
}

// 3-stage cp.async multistage fp16 GEMM with ldmatrix fragment feed.
// A: [M][K] row-major fp16.  Bt: [N][K] row-major fp16 (pre-transposed weight).
template<int BM, int BN, int BK, int WM, int WN, int EPI>
__global__ void __launch_bounds__((BM/WM)*(BN/WN)*32)
hgemm_kernel(const __half* __restrict__ A, const __half* __restrict__ Bt,
             float* __restrict__ Cg, int M, int N, int K,
             const float* __restrict__ bias, const float* __restrict__ addend)
{
    constexpr int WARPS_M = BM / WM;
    constexpr int WARPS_N = BN / WN;
    constexpr int NT = WARPS_M * WARPS_N * 32;
    constexpr int MD = WM / 16;
    constexpr int ND = WN / 8;
    static_assert(BK % 16 == 0, "BK multiple of 16");
    static_assert(ND % 2 == 0, "ND even for paired B ldmatrix");
    constexpr int AS = BK + 8;        // halves; row stride 144B -> LDSM conflict-free
    constexpr int BS = BK + 8;
    constexpr int STAGES = 3;
    constexpr int ASZ = BM * AS;      // halves
    constexpr int BSZ = BN * BS;
    constexpr int ACH = BM * BK / 8;  // 16B chunks
    constexpr int APT = ACH / NT;
    constexpr int BCH = BN * BK / 8;
    constexpr int BPT = (BCH + NT - 1) / NT;
    constexpr bool BFULL = (BCH % NT) == 0;

    extern __shared__ __half smem[];
    __half* sAbase = smem;
    __half* sBbase = smem + STAGES * ASZ;
    const uint32_t smemA_u32 = (uint32_t)__cvta_generic_to_shared(sAbase);
    const uint32_t smemB_u32 = (uint32_t)__cvta_generic_to_shared(sBbase);

    const int tid = threadIdx.x;
    const int bm = blockIdx.y * BM;
    const int bn = blockIdx.x * BN;
    const int warp = tid >> 5, lane = tid & 31;
    const int wm = (warp / WARPS_N) * WM;
    const int wn = (warp % WARPS_N) * WN;
    const int grp = lane >> 2, tg = lane & 3;
    const int KT = K / BK;

    // per-thread ldmatrix address components (in halves)
    const int a_row  = wm + (lane & 15);
    const int a_koff = (lane >> 4) << 3;                 // 0 or 8
    const int b_row  = wn + ((lane >> 4) << 3) + (lane & 7);
    const int b_koff = ((lane >> 3) & 1) << 3;           // 0 or 8

    float acc[MD][ND][4];
    #pragma unroll
    for (int i = 0; i < MD; i++)
        #pragma unroll
        for (int j = 0; j < ND; j++)
            #pragma unroll
            for (int e = 0; e < 4; e++) acc[i][j][e] = 0.f;

    auto issue = [&](int kt, int stage) {
        int k0 = kt * BK;
        __half* sA = sAbase + stage * ASZ;
        __half* sB = sBbase + stage * BSZ;
        #pragma unroll
        for (int i = 0; i < APT; i++) {
            int idx = tid + i * NT;
            int r = idx / (BK / 8), c8 = idx % (BK / 8);
            uint32_t dst = (uint32_t)__cvta_generic_to_shared(sA + r * AS + c8 * 8);
            const __half* src = A + (size_t)(bm + r) * K + k0 + c8 * 8;
            asm volatile("cp.async.cg.shared.global [%0], [%1], 16;\n"
                         :: "r"(dst), "l"(src));
        }
        #pragma unroll
        for (int i = 0; i < BPT; i++) {
            int idx = tid + i * NT;
            if (BFULL || idx < BCH) {
                int r = idx / (BK / 8), c8 = idx % (BK / 8);
                uint32_t dst = (uint32_t)__cvta_generic_to_shared(sB + r * BS + c8 * 8);
                const __half* src = Bt + (size_t)(bn + r) * K + k0 + c8 * 8;
                asm volatile("cp.async.cg.shared.global [%0], [%1], 16;\n"
                             :: "r"(dst), "l"(src));
            }
        }
        asm volatile("cp.async.commit_group;\n" ::: "memory");
    };

    issue(0, 0);
    issue(1, 1);
    asm volatile("cp.async.wait_group 1;\n" ::: "memory");
    __syncthreads();

    for (int kt = 0; kt < KT; kt++) {
        int stage = kt % STAGES;
        if (kt + 2 < KT) {
            issue(kt + 2, (kt + 2) % STAGES);
        } else {
            asm volatile("cp.async.commit_group;\n" ::: "memory");
        }
        const uint32_t aST = smemA_u32 + (stage * ASZ) * 2;
        const uint32_t bST = smemB_u32 + (stage * BSZ) * 2;
        const uint32_t aBase = aST + (a_row * AS + a_koff) * 2;
        const uint32_t bBase = bST + (b_row * BS + b_koff) * 2;
        #pragma unroll
        for (int ks = 0; ks < BK / 16; ks++) {
            uint32_t af[MD][4], bf[ND][2];
            #pragma unroll
            for (int md = 0; md < MD; md++)
                ldsm4(af[md][0], af[md][1], af[md][2], af[md][3],
                      aBase + (md * 16 * AS + ks * 16) * 2);
            #pragma unroll
            for (int nd = 0; nd < ND; nd += 2)
                ldsm4(bf[nd][0], bf[nd][1], bf[nd+1][0], bf[nd+1][1],
                      bBase + (nd * 8 * BS + ks * 16) * 2);
            #pragma unroll
            for (int md = 0; md < MD; md++)
                #pragma unroll
                for (int nd = 0; nd < ND; nd++)
                    mma_f16(acc[md][nd], af[md], bf[nd]);
        }
        asm volatile("cp.async.wait_group 1;\n" ::: "memory");
        __syncthreads();
    }

    // epilogue
    #pragma unroll
    for (int md = 0; md < MD; md++) {
        #pragma unroll
        for (int nd = 0; nd < ND; nd++) {
            int row0 = bm + wm + md * 16 + grp;
            int col  = bn + wn + nd * 8 + 2 * tg;
            float2 p;
            p.x = epi_apply<EPI>(acc[md][nd][0], row0, col,     N, bias, addend);
            p.y = epi_apply<EPI>(acc[md][nd][1], row0, col + 1, N, bias, addend);
            *(float2*)(Cg + (size_t)row0 * N + col) = p;
            float2 q;
            q.x = epi_apply<EPI>(acc[md][nd][2], row0 + 8, col,     N, bias, addend);
            q.y = epi_apply<EPI>(acc[md][nd][3], row0 + 8, col + 1, N, bias, addend);
            *(float2*)(Cg + (size_t)(row0 + 8) * N + col) = q;
        }
    }
}

// --------------------------------------------------------------- scan ------
__global__ void scanA_kernel(const float* __restrict__ logA) {
    int di = blockIdx.x * 128 + threadIdx.x;
    int c = blockIdx.y, b = blockIdx.z;
    float Av = -__expf(logA[di]);
    float h[DSTATE];
    #pragma unroll
    for (int s = 0; s < DSTATE; s++) h[s] = 0.f;
    float P = 1.f;
    int rbase = b * SEQ_T + c * TCHUNK;
    for (int t = 0; t < TCHUNK; t++) {
        int row = rbase + t;
        float dtv = g_dt[row * DIM + di];
        float xv  = g_xc[row * DIM + di];
        float decay = __expf(fminf(dtv * Av, 0.f));
        float u = dtv * xv;
        const float4* bc = (const float4*)(g_bc + row * 32);
        float4 b0 = bc[0], b1 = bc[1], b2 = bc[2], b3 = bc[3];
        float Bv[DSTATE] = {b0.x,b0.y,b0.z,b0.w, b1.x,b1.y,b1.z,b1.w,
                            b2.x,b2.y,b2.z,b2.w, b3.x,b3.y,b3.z,b3.w};
        P *= decay;
        #pragma unroll
        for (int s = 0; s < DSTATE; s++) h[s] = h[s] * decay + u * Bv[s];
    }
    int o = ((b * NCHUNK + c) * DSTATE) * DIM + di;
    #pragma unroll
    for (int s = 0; s < DSTATE; s++) g_hend[o + s * DIM] = h[s];
    g_Pp[(b * NCHUNK + c) * DIM + di] = P;
}

__global__ void combine_kernel() {
    int idx = blockIdx.x * 256 + threadIdx.x;   // NBATCH*DSTATE*DIM
    int di = idx % DIM;
    int s  = (idx / DIM) % DSTATE;
    int b  = idx / (DIM * DSTATE);
    float h = 0.f;
    g_hinit[((b * NCHUNK + 0) * DSTATE + s) * DIM + di] = 0.f;
    for (int c = 1; c < NCHUNK; c++) {
        float he = g_hend[((b * NCHUNK + c - 1) * DSTATE + s) * DIM + di];
        float Pv = g_Pp [ (b * NCHUNK + c - 1) * DIM + di];
        h = he + Pv * h;
        g_hinit[((b * NCHUNK + c) * DSTATE + s) * DIM + di] = h;
    }
}

__global__ void scanC_kernel(const float* __restrict__ logA,
                             const float* __restrict__ Dp) {
    int di = blockIdx.x * 128 + threadIdx.x;
    int c = blockIdx.y, b = blockIdx.z;
    float Av = -__expf(logA[di]);
    float Dv = Dp[di];
    float h[DSTATE];
    int o = ((b * NCHUNK + c) * DSTATE) * DIM + di;
    #pragma unroll
    for (int s = 0; s < DSTATE; s++) h[s] = g_hinit[o + s * DIM];
    int rbase = b * SEQ_T + c * TCHUNK;
    for (int t = 0; t < TCHUNK; t++) {
        int row = rbase + t;
        float dtv = g_dt[row * DIM + di];
        float xv  = g_xc[row * DIM + di];
        float decay = __expf(fminf(dtv * Av, 0.f));
        float u = dtv * xv;
        const float4* bc = (const float4*)(g_bc + row * 32);
        float4 b0 = bc[0], b1 = bc[1], b2 = bc[2], b3 = bc[3];
        float4 c0 = bc[4], c1 = bc[5], c2 = bc[6], c3 = bc[7];
        float Bv[DSTATE] = {b0.x,b0.y,b0.z,b0.w, b1.x,b1.y,b1.z,b1.w,
                            b2.x,b2.y,b2.z,b2.w, b3.x,b3.y,b3.z,b3.w};
        float Cv[DSTATE] = {c0.x,c0.y,c0.z,c0.w, c1.x,c1.y,c1.z,c1.w,
                            c2.x,c2.y,c2.z,c2.w, c3.x,c3.y,c3.z,c3.w};
        float y = 0.f;
        #pragma unroll
        for (int s = 0; s < DSTATE; s++) {
            h[s] = h[s] * decay + u * Bv[s];
            y += h[s] * Cv[s];
        }
        float zv = g_xz[row * (2 * DIM) + DIM + di];
        float sg = zv / (1.f + __expf(-zv));
        g_ygh[row * DIM + di] = __float2half_rn((y + xv * Dv) * sg);
    }
}

// ----------------------------------------------------------------- launch ---
static inline int hgemm_smem_bytes(int BM, int BN, int BK) {
    return 3 * (BM * (BK + 8) + BN * (BK + 8)) * 2;
}

extern "C" void kernel_launch(void* const* d_in, const int* in_sizes, int n_in,
                              void* d_out, int out_size) {
    const float* x      = (const float*)d_in[0];
    const float* ln_g   = (const float*)d_in[1];
    const float* ln_b   = (const float*)d_in[2];
    const float* W_in   = (const float*)d_in[3];
    const float* conv_w = (const float*)d_in[4];
    const float* conv_b = (const float*)d_in[5];
    const float* dt_w   = (const float*)d_in[6];
    const float* dt_b   = (const float*)d_in[7];
    const float* B_w    = (const float*)d_in[8];
    const float* C_w    = (const float*)d_in[9];
    const float* log_A  = (const float*)d_in[10];
    const float* D_par  = (const float*)d_in[11];
    const float* W_out  = (const float*)d_in[12];
    float* out = (float*)d_out;

    __half *p_xnh, *p_xch, *p_bcwh, *p_ygh, *p_w1t, *p_wdt, *p_wot;
    float *p_xz, *p_dt, *p_bc;
    cudaGetSymbolAddress((void**)&p_xnh,  g_xnh);
    cudaGetSymbolAddress((void**)&p_xz,   g_xz);
    cudaGetSymbolAddress((void**)&p_xch,  g_xch);
    cudaGetSymbolAddress((void**)&p_dt,   g_dt);
    cudaGetSymbolAddress((void**)&p_bc,   g_bc);
    cudaGetSymbolAddress((void**)&p_bcwh, g_bcwh);
    cudaGetSymbolAddress((void**)&p_ygh,  g_ygh);
    cudaGetSymbolAddress((void**)&p_w1t,  g_w1t);
    cudaGetSymbolAddress((void**)&p_wdt,  g_wdt);
    cudaGetSymbolAddress((void**)&p_wot,  g_wot);

    int smem_big   = hgemm_smem_bytes(128, 128, 64);   // 110,592 B
    int smem_small = hgemm_smem_bytes(64, 32, 64);     //  41,472 B
    cudaFuncSetAttribute(hgemm_kernel<128,128,64,64,64,0>,
                         cudaFuncAttributeMaxDynamicSharedMemorySize, smem_big);
    cudaFuncSetAttribute(hgemm_kernel<128,128,64,64,64,1>,
                         cudaFuncAttributeMaxDynamicSharedMemorySize, smem_big);
    cudaFuncSetAttribute(hgemm_kernel<128,128,64,64,64,2>,
                         cudaFuncAttributeMaxDynamicSharedMemorySize, smem_big);
    cudaFuncSetAttribute(hgemm_kernel<64,32,64,32,16,0>,
                         cudaFuncAttributeMaxDynamicSharedMemorySize, smem_small);

    // 0. fused prep: weight transposes -> [N][K] fp16 + [B|C]^T concat
    prep_kernel<<<4096 + 128, dim3(32, 8)>>>(W_in, dt_w, W_out, B_w, C_w);

    // 1. layernorm (fp16 output)
    ln_kernel<<<BT, 256>>>(x, ln_g, ln_b);

    // 2. xz = xn @ W_in   [4096 x 2048]
    hgemm_kernel<128,128,64,64,64,0><<<dim3(2*DIM/128, BT/128), 128, smem_big>>>(
        p_xnh, p_w1t, p_xz, BT, 2*DIM, D_MODEL, nullptr, nullptr);

    // 3. causal depthwise conv + silu (fp32 + fp16 copies)
    conv_silu_kernel<<<BT/8, 256>>>(conv_w, conv_b);

    // 4. dt = softplus(xch @ dt_w + dt_b)
    hgemm_kernel<128,128,64,64,64,1><<<dim3(DIM/128, BT/128), 128, smem_big>>>(
        p_xch, p_wdt, p_dt, BT, DIM, DIM, dt_b, nullptr);

    // 5. [Bm|Cm] = xch @ [B_w|C_w]   [4096 x 32]
    hgemm_kernel<64,32,64,32,16,0><<<dim3(1, BT/64), 128, smem_small>>>(
        p_xch, p_bcwh, p_bc, BT, 32, DIM, nullptr, nullptr);

    // 6. chunked selective scan (exact; NCHUNK=64)
    scanA_kernel<<<dim3(DIM/128, NCHUNK, NBATCH), 128>>>(log_A);
    combine_kernel<<<NBATCH*DSTATE*DIM/256, 256>>>();
    scanC_kernel<<<dim3(DIM/128, NCHUNK, NBATCH), 128>>>(log_A, D_par);

    // 7. out = x + yg @ W_out
    hgemm_kernel<128,128,64,64,64,2><<<dim3(DIM/128, BT/128), 128, smem_big>>>(
        p_ygh, p_wot, out, BT, DIM, DIM, nullptr, x);
}